// round 12
// baseline (speedup 1.0000x reference)
#include <cuda_runtime.h>
#include <cuda_bf16.h>
#include <math.h>

// ============================================================================
// PredictiveReasoningBlock — pipeline: precompute / stats+transpose / atten / conv.
// Shapes: B=4096, D=32, T=9, L=24, H=8, HD=4.
// Round 11: atten occupancy 3->4 blocks/SM (2-pass row tiles to cap regs),
// conv weights vectorized via [kt][i4][o][d] layout (LDG.128).
// ============================================================================

#define MAXB 4096

__device__ float gA32[1024];
__device__ float gBmixr[376];
__device__ float gPPC[768];
__device__ float gCWT2[9216];     // [((kt*8+i4)*32+o)*4+d] = conv_w[(o,i4*4+d,kt)]
__device__ float gWQT[1024];      // [i][j] = q_w[j][i]
__device__ float gWKT[1024];
__device__ float gWVT[1024];
__device__ float gWMT[1024];
__device__ float gSDL[MAXB * 32];
__device__ float gXT[(size_t)MAXB * 6912];    // x transposed [b][tl][c]
__device__ float gXATT[(size_t)MAXB * 6912];  // x_att [b][tl][c]

__constant__ float cWL[64];
__constant__ float cWC[64];

__device__ __forceinline__ float geluf(float x) {
    return 0.5f * x * (1.0f + erff(x * 0.7071067811865476f));
}
__device__ __forceinline__ float sigmoidf_(float x) {
    return 1.0f / (1.0f + __expf(-x));
}

// ---------------------------------------------------------------------------
// Kernel A: batch-invariant precompute
// ---------------------------------------------------------------------------
__global__ void prb_precompute(const float* __restrict__ Wc,
                               const float* __restrict__ WL,
                               const float* __restrict__ rpb,
                               const float* __restrict__ conv_w,
                               const float* __restrict__ conv_b,
                               const float* __restrict__ pre_prompt,
                               const float* __restrict__ q_w,
                               const float* __restrict__ k_w,
                               const float* __restrict__ v_w,
                               const float* __restrict__ m_w) {
    int tid = threadIdx.x;
    if (tid < 32) {
        float a[32];
        float rs = 0.f;
#pragma unroll
        for (int j = 0; j < 32; ++j) {
            float w = Wc[tid * 32 + j];
            float sp = (w > 20.f) ? w : log1pf(expf(w));
            if (j == tid) sp = 0.f;
            a[j] = sp;
            rs += sp;
        }
        float inv = 0.9f / (rs + 1e-6f);
#pragma unroll
        for (int j = 0; j < 32; ++j) gA32[tid * 32 + j] = a[j] * inv;
    }
    for (int idx = tid; idx < 376; idx += blockDim.x) {
        int Ho = idx / 47, r = idx % 47;
        float s = 0.f;
#pragma unroll
        for (int h = 0; h < 8; ++h) s += WL[h * 8 + Ho] * rpb[h * 47 + r];
        gBmixr[idx] = s;
    }
    for (int idx = tid; idx < 768; idx += blockDim.x) {
        int o = idx / 24, l = idx % 24;
        float s = conv_b[o];
#pragma unroll
        for (int i = 0; i < 32; ++i)
            s += conv_w[(o * 32 + i) * 9 + 8] * pre_prompt[i * 24 + l];
        gPPC[idx] = s;
    }
    for (int idx = tid; idx < 9216; idx += blockDim.x) {
        int d  = idx & 3;
        int o  = (idx >> 2) & 31;
        int i4 = (idx >> 7) & 7;
        int kt = idx >> 10;
        gCWT2[idx] = conv_w[(o * 32 + i4 * 4 + d) * 9 + kt];
    }
    for (int idx = tid; idx < 1024; idx += blockDim.x) {
        int i = idx >> 5, j = idx & 31;
        gWQT[idx] = q_w[j * 32 + i];
        gWKT[idx] = k_w[j * 32 + i];
        gWVT[idx] = v_w[j * 32 + i];
        gWMT[idx] = m_w[j * 32 + i];
    }
}

// ---------------------------------------------------------------------------
// Kernel B: stats + scalar chain -> gSDL ; transpose x -> gXT [b][tl][c]
// ---------------------------------------------------------------------------
__global__ __launch_bounds__(256)
void prb_stats(const float* __restrict__ x,
               const float* __restrict__ ln_g,  const float* __restrict__ ln_b,
               const float* __restrict__ rp_w1, const float* __restrict__ rp_b1,
               const float* __restrict__ rp_w2, const float* __restrict__ rp_b2,
               const float* __restrict__ mask_w, const float* __restrict__ mask_b,
               const float* __restrict__ val_w1, const float* __restrict__ val_b1,
               const float* __restrict__ val_w2, const float* __restrict__ val_b2,
               const float* __restrict__ fuse_gate)
{
    __shared__ float fs[7128];            // [216][33]
    __shared__ float psum[256], psq[256];
    __shared__ float aA[1056];            // [32][33]
    __shared__ float vc1[32], vc2[32], vc3[32];
    const int tid = threadIdx.x;
    const size_t base = (size_t)blockIdx.x * 6912;

    for (int idx = tid; idx < 6912; idx += 256) {
        int c = idx / 216, tl = idx % 216;
        fs[tl * 33 + c] = x[base + idx];
    }
    for (int idx = tid; idx < 1024; idx += 256) {
        int j = idx >> 5, i = idx & 31;
        aA[j * 33 + i] = gA32[idx];
    }
    __syncthreads();

    {
        int c = tid >> 3, part = tid & 7;
        float s = 0.f, sq = 0.f;
        int tl0 = part * 27;
#pragma unroll 9
        for (int k2 = 0; k2 < 27; ++k2) {
            float v = fs[(tl0 + k2) * 33 + c];
            s += v; sq += v * v;
        }
        psum[c * 8 + part] = s;
        psq [c * 8 + part] = sq;
    }
    __syncthreads();

    if (tid < 32) {
        const int c = tid;
        float s = 0.f, sq = 0.f;
#pragma unroll
        for (int p = 0; p < 8; ++p) { s += psum[c * 8 + p]; sq += psq[c * 8 + p]; }
        float pooled = s * (1.f / 216.f);
        float varu = (sq - s * s * (1.f / 216.f)) * (1.f / 215.f);
        float scalec = fmaxf(sqrtf(fmaxf(varu, 0.f)), 1e-3f);

        float mu = pooled;
#pragma unroll
        for (int o = 16; o > 0; o >>= 1) mu += __shfl_xor_sync(0xffffffffu, mu, o);
        mu *= (1.f / 32.f);
        float d = pooled - mu;
        float var = d * d;
#pragma unroll
        for (int o = 16; o > 0; o >>= 1) var += __shfl_xor_sync(0xffffffffu, var, o);
        var *= (1.f / 32.f);
        float pn = d * rsqrtf(var + 1e-5f) * ln_g[c] + ln_b[c];
        vc1[c] = pn; __syncwarp();

        float acc = rp_b1[c];
#pragma unroll
        for (int i = 0; i < 32; ++i) acc += vc1[i] * rp_w1[c * 32 + i];
        vc2[c] = geluf(acc); __syncwarp();

        acc = rp_b2[c];
#pragma unroll
        for (int i = 0; i < 32; ++i) acc += vc2[i] * rp_w2[c * 32 + i];
        vc1[c] = acc; __syncwarp();       // pooled_rule

        acc = mask_b[c];
#pragma unroll
        for (int i = 0; i < 32; ++i) acc += vc1[i] * mask_w[c * 32 + i];
        float M = sigmoidf_(acc);

        acc = val_b1[c];
#pragma unroll
        for (int i = 0; i < 32; ++i) acc += vc1[i] * val_w1[c * 32 + i];
        vc2[c] = geluf(acc); __syncwarp();

        acc = val_b2[c];
#pragma unroll
        for (int i = 0; i < 32; ++i) acc += vc2[i] * val_w2[c * 32 + i];
        float v32 = tanhf(acc) * scalec + pooled;
        float xdo = (1.f - M) * pooled + M * v32;

        float y = xdo;
#pragma unroll
        for (int it = 0; it < 3; ++it) {
            vc3[c] = y; __syncwarp();
            float a2 = xdo;
#pragma unroll
            for (int j = 0; j < 32; ++j) a2 += vc3[j] * aA[c * 33 + j];
            y = a2;
            __syncwarp();
        }
        gSDL[blockIdx.x * 32 + c] = sigmoidf_(fuse_gate[0]) * (y - pooled);
    }

    for (int idx = tid; idx < 6912; idx += 256) {
        int tl = idx >> 5, c = idx & 31;
        gXT[base + idx] = fs[tl * 33 + c];
    }
}

// ---------------------------------------------------------------------------
// Kernel C: attention, one b per 192-thread block, 3-t chunks, 4 blocks/SM
// ---------------------------------------------------------------------------
#define A_Q3   0        // [72][36]
#define A_K3   2592
#define A_V3   5184
#define A_SMX  7776     // [8][676]
#define A_BMX  13184    // 376 pad 384
#define A_SDL  13568    // 32
#define A_TOT  13600

__global__ __launch_bounds__(192, 4)
void prb_atten(const float* __restrict__ q_b, const float* __restrict__ k_b,
               const float* __restrict__ v_b, const float* __restrict__ m_b)
{
    extern __shared__ float sm[];
    float* q3  = sm + A_Q3;
    float* k3  = sm + A_K3;
    float* v3  = sm + A_V3;
    float* smx = sm + A_SMX;
    float* bmx = sm + A_BMX;
    float* sdl = sm + A_SDL;

    const int tid = threadIdx.x;
    const int b = blockIdx.x;
    const int j32 = tid & 31;
    const int w6  = tid >> 5;

    const float bq_ = q_b[j32];
    const float bk_ = k_b[j32];
    const float bv_ = v_b[j32];
    const float bm_ = m_b[j32];

    for (int idx = tid; idx < 376; idx += 192) bmx[idx] = gBmixr[idx];
    if (tid < 32) sdl[tid] = gSDL[b * 32 + tid];
    __syncthreads();

    const float* xb = gXT + (size_t)b * 6912;
    float* ob = gXATT + (size_t)b * 6912;

    for (int tc = 0; tc < 3; ++tc) {
        // ---- qkv: 12 rows/warp in 2 passes of 6, cosine norm via shfl ----
#pragma unroll
        for (int pass = 0; pass < 2; ++pass) {
            const int r0 = w6 * 12 + pass * 6;
            const float* xrow = xb + (tc * 72 + r0) * 32;
            float aq[6], ak[6], av[6];
#pragma unroll
            for (int r = 0; r < 6; ++r) { aq[r] = bq_; ak[r] = bk_; av[r] = bv_; }
#pragma unroll
            for (int i4 = 0; i4 < 8; ++i4) {
                float4 sd4 = *(const float4*)&sdl[i4 * 4];
                float wq0 = gWQT[(i4*4+0)*32 + j32], wq1 = gWQT[(i4*4+1)*32 + j32];
                float wq2 = gWQT[(i4*4+2)*32 + j32], wq3 = gWQT[(i4*4+3)*32 + j32];
                float wk0 = gWKT[(i4*4+0)*32 + j32], wk1 = gWKT[(i4*4+1)*32 + j32];
                float wk2 = gWKT[(i4*4+2)*32 + j32], wk3 = gWKT[(i4*4+3)*32 + j32];
                float wv0 = gWVT[(i4*4+0)*32 + j32], wv1 = gWVT[(i4*4+1)*32 + j32];
                float wv2 = gWVT[(i4*4+2)*32 + j32], wv3 = gWVT[(i4*4+3)*32 + j32];
#pragma unroll
                for (int r = 0; r < 6; ++r) {
                    float4 f4 = *(const float4*)(xrow + r * 32 + i4 * 4);
                    float f0 = f4.x + sd4.x, f1 = f4.y + sd4.y;
                    float f2 = f4.z + sd4.z, f3 = f4.w + sd4.w;
                    aq[r] = fmaf(f0, wq0, aq[r]); aq[r] = fmaf(f1, wq1, aq[r]);
                    aq[r] = fmaf(f2, wq2, aq[r]); aq[r] = fmaf(f3, wq3, aq[r]);
                    ak[r] = fmaf(f0, wk0, ak[r]); ak[r] = fmaf(f1, wk1, ak[r]);
                    ak[r] = fmaf(f2, wk2, ak[r]); ak[r] = fmaf(f3, wk3, ak[r]);
                    av[r] = fmaf(f0, wv0, av[r]); av[r] = fmaf(f1, wv1, av[r]);
                    av[r] = fmaf(f2, wv2, av[r]); av[r] = fmaf(f3, wv3, av[r]);
                }
            }
#pragma unroll
            for (int r = 0; r < 6; ++r) {
                float n2 = aq[r] * aq[r];
                n2 += __shfl_xor_sync(0xffffffffu, n2, 1);
                n2 += __shfl_xor_sync(0xffffffffu, n2, 2);
                aq[r] *= 0.5f / fmaxf(sqrtf(n2), 1e-12f);   // 1/sqrt(HD)=0.5 folded
                n2 = ak[r] * ak[r];
                n2 += __shfl_xor_sync(0xffffffffu, n2, 1);
                n2 += __shfl_xor_sync(0xffffffffu, n2, 2);
                ak[r] *= 1.f / fmaxf(sqrtf(n2), 1e-12f);
                n2 = av[r] * av[r];
                n2 += __shfl_xor_sync(0xffffffffu, n2, 1);
                n2 += __shfl_xor_sync(0xffffffffu, n2, 2);
                av[r] *= 1.f / fmaxf(sqrtf(n2), 1e-12f);
                q3[(r0 + r) * 36 + j32] = aq[r];
                k3[(r0 + r) * 36 + j32] = ak[r];
                v3[(r0 + r) * 36 + j32] = av[r];
            }
        }
        __syncthreads();

        for (int t3 = 0; t3 < 3; ++t3) {
            const int ro = t3 * 24;

            // ---- 4c: logits + W_logit mix (constant port) ----
            {
                const int i = tid >> 3, jg = tid & 7;
                float raw[3][8];
#pragma unroll
                for (int h = 0; h < 8; ++h) {
                    float4 qh = *(const float4*)&q3[(ro + i) * 36 + h * 4];
#pragma unroll
                    for (int r = 0; r < 3; ++r) {
                        float4 kv = *(const float4*)&k3[(ro + jg * 3 + r) * 36 + h * 4];
                        raw[r][h] = qh.x*kv.x + qh.y*kv.y + qh.z*kv.z + qh.w*kv.w;
                    }
                }
#pragma unroll
                for (int Ho = 0; Ho < 8; ++Ho) {
#pragma unroll
                    for (int r = 0; r < 3; ++r) {
                        float acc = 0.f;
#pragma unroll
                        for (int h = 0; h < 8; ++h)
                            acc = fmaf(raw[r][h], cWL[h * 8 + Ho], acc);
                        smx[Ho * 676 + i * 28 + jg * 3 + r] = acc;
                    }
                }
            }
            __syncthreads();

            // ---- 4d: softmax over j with rel-pos bias ----
            {
                const int Ho = tid / 24, i = tid % 24;
                float* row = &smx[Ho * 676 + i * 28];
                const float* brow = &bmx[Ho * 47 + i + 23];
                float e[24];
                {
                    const float4* rp = (const float4*)row;
#pragma unroll
                    for (int q4 = 0; q4 < 6; ++q4) {
                        float4 v4 = rp[q4];
                        e[q4*4+0] = v4.x; e[q4*4+1] = v4.y;
                        e[q4*4+2] = v4.z; e[q4*4+3] = v4.w;
                    }
                }
                float mx = -1e30f;
#pragma unroll
                for (int j = 0; j < 24; ++j) {
                    e[j] += brow[-j];
                    mx = fmaxf(mx, e[j]);
                }
                float ssum = 0.f;
#pragma unroll
                for (int j = 0; j < 24; ++j) { e[j] = __expf(e[j] - mx); ssum += e[j]; }
                float inv = 1.f / ssum;
                float4* wp = (float4*)row;
#pragma unroll
                for (int q4 = 0; q4 < 6; ++q4) {
                    float4 v4;
                    v4.x = e[q4*4+0] * inv; v4.y = e[q4*4+1] * inv;
                    v4.z = e[q4*4+2] * inv; v4.w = e[q4*4+3] * inv;
                    wp[q4] = v4;
                }
            }
            __syncthreads();

            // ---- 4e: W_ctx mix in place (constant port) ----
            {
                const int i = tid >> 3, jg = tid & 7;
                float sv[3][8];
#pragma unroll
                for (int h = 0; h < 8; ++h)
#pragma unroll
                    for (int r = 0; r < 3; ++r)
                        sv[r][h] = smx[h * 676 + i * 28 + jg * 3 + r];
#pragma unroll
                for (int Ho = 0; Ho < 8; ++Ho) {
#pragma unroll
                    for (int r = 0; r < 3; ++r) {
                        float acc = 0.f;
#pragma unroll
                        for (int h = 0; h < 8; ++h)
                            acc = fmaf(sv[r][h], cWC[h * 8 + Ho], acc);
                        smx[Ho * 676 + i * 28 + jg * 3 + r] = acc;
                    }
                }
            }
            __syncthreads();

            // ---- 4f: AV -> att into q3 rows of this t3 (4 rows/warp) ----
            {
                const int h = j32 >> 2;
                const int rf = w6 * 4;
                float acc[4] = {0.f, 0.f, 0.f, 0.f};
#pragma unroll
                for (int j4 = 0; j4 < 6; ++j4) {
                    float s4[4][4];
#pragma unroll
                    for (int r = 0; r < 4; ++r) {
                        float4 tv = *(const float4*)&smx[h * 676 + (rf + r) * 28 + j4 * 4];
                        s4[r][0] = tv.x; s4[r][1] = tv.y; s4[r][2] = tv.z; s4[r][3] = tv.w;
                    }
#pragma unroll
                    for (int s = 0; s < 4; ++s) {
                        float vv = v3[(ro + j4 * 4 + s) * 36 + j32];
#pragma unroll
                        for (int r = 0; r < 4; ++r)
                            acc[r] = fmaf(s4[r][s], vv, acc[r]);
                    }
                }
#pragma unroll
                for (int r = 0; r < 4; ++r)
                    q3[(ro + rf + r) * 36 + j32] = acc[r];
            }
            __syncthreads();
        }

        // ---- 4g: output projection (2 passes of 6 rows) -> gXATT ----
#pragma unroll
        for (int pass = 0; pass < 2; ++pass) {
            const int r0 = w6 * 12 + pass * 6;
            float am[6];
#pragma unroll
            for (int r = 0; r < 6; ++r) am[r] = bm_;
#pragma unroll
            for (int i4 = 0; i4 < 8; ++i4) {
                float wm0 = gWMT[(i4*4+0)*32 + j32], wm1 = gWMT[(i4*4+1)*32 + j32];
                float wm2 = gWMT[(i4*4+2)*32 + j32], wm3 = gWMT[(i4*4+3)*32 + j32];
#pragma unroll
                for (int r = 0; r < 6; ++r) {
                    float4 a4 = *(const float4*)&q3[(r0 + r) * 36 + i4 * 4];
                    am[r] = fmaf(a4.x, wm0, am[r]); am[r] = fmaf(a4.y, wm1, am[r]);
                    am[r] = fmaf(a4.z, wm2, am[r]); am[r] = fmaf(a4.w, wm3, am[r]);
                }
            }
#pragma unroll
            for (int r = 0; r < 6; ++r)
                ob[(tc * 72 + r0 + r) * 32 + j32] = am[r];
        }
        __syncthreads();
    }
}

// ---------------------------------------------------------------------------
// Kernel D: conv over contexts + token linear + output
// ---------------------------------------------------------------------------
#define D_FS    0        // [216][36]
#define D_PPC   7776     // [32][25]
#define D_P1    8576
#define D_P2    9376
#define D_PWT   10176    // [24][25]
#define D_PBF   10776
#define D_TOTAL 10808

__global__ __launch_bounds__(256, 4)
void prb_conv(const float* __restrict__ p_w, const float* __restrict__ p_b,
              float* __restrict__ out)
{
    extern __shared__ float sm[];
    const int tid = threadIdx.x;
    const size_t base = (size_t)blockIdx.x * 6912;

    float* fs  = sm + D_FS;
    float* ppc = sm + D_PPC;
    float* p1  = sm + D_P1;
    float* p2  = sm + D_P2;
    float* pwT = sm + D_PWT;
    float* pbf = sm + D_PBF;

    const int j32 = tid & 31;
    const int g8  = tid >> 5;

    for (int idx = tid; idx < 6912; idx += 256) {
        int tl = idx >> 5, c = idx & 31;
        fs[tl * 36 + c] = gXATT[base + idx];
    }
    for (int idx = tid; idx < 768; idx += 256) {
        int o = idx / 24, l = idx % 24;
        ppc[o * 25 + l] = gPPC[idx];
    }
    for (int idx = tid; idx < 576; idx += 256) {
        int lo = idx / 24, l = idx % 24;
        pwT[l * 25 + lo] = p_w[idx];
    }
    if (tid < 24) pbf[tid] = p_b[tid];
    __syncthreads();

    {
        const int lbase = g8 * 3;
        float acc[3];
#pragma unroll
        for (int r = 0; r < 3; ++r) acc[r] = ppc[j32 * 25 + lbase + r];
#pragma unroll
        for (int kt = 0; kt < 8; ++kt) {
#pragma unroll
            for (int i4 = 0; i4 < 8; ++i4) {
                float4 w4 = *(const float4*)&gCWT2[(((kt * 8) + i4) * 32 + j32) * 4];
#pragma unroll
                for (int r = 0; r < 3; ++r) {
                    float4 f4 = *(const float4*)&fs[(kt * 24 + lbase + r) * 36 + i4 * 4];
                    acc[r] = fmaf(f4.x, w4.x, acc[r]);
                    acc[r] = fmaf(f4.y, w4.y, acc[r]);
                    acc[r] = fmaf(f4.z, w4.z, acc[r]);
                    acc[r] = fmaf(f4.w, w4.w, acc[r]);
                }
            }
        }
#pragma unroll
        for (int r = 0; r < 3; ++r)
            p1[j32 * 25 + lbase + r] = fmaxf(acc[r], 0.f);
    }
    __syncthreads();

    for (int idx = tid; idx < 768; idx += 256) {
        int o = idx / 24, lo = idx % 24;
        float acc = pbf[lo];
#pragma unroll
        for (int l = 0; l < 24; ++l)
            acc = fmaf(p1[o * 25 + l], pwT[l * 25 + lo], acc);
        p2[o * 25 + lo] = acc;
    }
    __syncthreads();

    for (int idx = tid; idx < 6912; idx += 256) {
        int c = idx / 216, tl = idx % 216;
        float v = fs[tl * 36 + c];
        if (tl >= 192) v -= p2[c * 25 + (tl - 192)];
        out[base + idx] = v;
    }
}

extern "C" void kernel_launch(void* const* d_in, const int* in_sizes, int n_in,
                              void* d_out, int out_size) {
    const float* x        = (const float*)d_in[0];
    const float* ln_g     = (const float*)d_in[1];
    const float* ln_b     = (const float*)d_in[2];
    const float* rp_w1    = (const float*)d_in[3];
    const float* rp_b1    = (const float*)d_in[4];
    const float* rp_w2    = (const float*)d_in[5];
    const float* rp_b2    = (const float*)d_in[6];
    const float* W_causal = (const float*)d_in[7];
    const float* mask_w   = (const float*)d_in[8];
    const float* mask_b   = (const float*)d_in[9];
    const float* val_w1   = (const float*)d_in[10];
    const float* val_b1   = (const float*)d_in[11];
    const float* val_w2   = (const float*)d_in[12];
    const float* val_b2   = (const float*)d_in[13];
    const float* fuse_g   = (const float*)d_in[14];
    const float* q_w      = (const float*)d_in[15];
    const float* q_b      = (const float*)d_in[16];
    const float* k_w      = (const float*)d_in[17];
    const float* k_b      = (const float*)d_in[18];
    const float* v_w      = (const float*)d_in[19];
    const float* v_b      = (const float*)d_in[20];
    const float* m_w      = (const float*)d_in[21];
    const float* m_b      = (const float*)d_in[22];
    const float* W_logit  = (const float*)d_in[23];
    const float* W_ctx    = (const float*)d_in[24];
    const float* rpb      = (const float*)d_in[25];
    const float* pre_p    = (const float*)d_in[26];
    const float* conv_w   = (const float*)d_in[27];
    const float* conv_b   = (const float*)d_in[28];
    const float* p_w      = (const float*)d_in[29];
    const float* p_b      = (const float*)d_in[30];
    float* out = (float*)d_out;

    int B = in_sizes[0] / 6912;

    cudaFuncSetAttribute(prb_atten, cudaFuncAttributeMaxDynamicSharedMemorySize,
                         A_TOT * 4);
    cudaFuncSetAttribute(prb_conv, cudaFuncAttributeMaxDynamicSharedMemorySize,
                         D_TOTAL * 4);

    cudaMemcpyToSymbolAsync(cWL, W_logit, 64 * sizeof(float), 0,
                            cudaMemcpyDeviceToDevice);
    cudaMemcpyToSymbolAsync(cWC, W_ctx, 64 * sizeof(float), 0,
                            cudaMemcpyDeviceToDevice);

    prb_precompute<<<1, 256>>>(W_causal, W_logit, rpb, conv_w, conv_b, pre_p,
                               q_w, k_w, v_w, m_w);
    prb_stats<<<B, 256>>>(x, ln_g, ln_b, rp_w1, rp_b1, rp_w2, rp_b2,
                          mask_w, mask_b, val_w1, val_b1, val_w2, val_b2, fuse_g);
    prb_atten<<<B, 192, A_TOT * 4>>>(q_b, k_b, v_b, m_b);
    prb_conv<<<B, 256, D_TOTAL * 4>>>(p_w, p_b, out);
}

// round 13
// speedup vs baseline: 1.1446x; 1.1446x over previous
#include <cuda_runtime.h>
#include <cuda_bf16.h>
#include <math.h>

// ============================================================================
// PredictiveReasoningBlock fused kernel. One CTA per batch element (monolith,
// R6 structure). Round 12: packed float4 weight layouts (¼ weight-load
// instructions in qkv/m-proj/conv) + conflict-free phase-1/7 copies.
// Shapes: B=4096, D=32, T=9, L=24, H=8, HD=4.
// ============================================================================

#define NTHR 256

__device__ float gA32[1024];     // 0.9*softplus(W_causal)*(1-I), row-normalized
__device__ float gBmixr[376];    // sum_h W_logit[h,Ho]*rel_pos_bias[h,r] (8x47)
__device__ float gPPC[768];      // conv_b[o] + sum_i conv_w[o,i,8]*pre_prompt[i,l]
__device__ float gWQKV4[3072];   // [m][i4][lane][4]: W_m[lane][i4*4+d]
__device__ float gWM4[1024];     // [i4][lane][4]
__device__ float gCWT2[9216];    // [kt][i4][o][4] = conv_w[o][i4*4+d][kt]

__device__ __forceinline__ float geluf(float x) {
    return 0.5f * x * (1.0f + erff(x * 0.7071067811865476f));
}
__device__ __forceinline__ float sigmoidf_(float x) {
    return 1.0f / (1.0f + __expf(-x));
}

__global__ void prb_precompute(const float* __restrict__ Wc,
                               const float* __restrict__ WL,
                               const float* __restrict__ rpb,
                               const float* __restrict__ conv_w,
                               const float* __restrict__ conv_b,
                               const float* __restrict__ pre_prompt,
                               const float* __restrict__ q_w,
                               const float* __restrict__ k_w,
                               const float* __restrict__ v_w,
                               const float* __restrict__ m_w) {
    int tid = threadIdx.x;
    if (tid < 32) {
        float a[32];
        float rs = 0.f;
#pragma unroll
        for (int j = 0; j < 32; ++j) {
            float w = Wc[tid * 32 + j];
            float sp = (w > 20.f) ? w : log1pf(expf(w));
            if (j == tid) sp = 0.f;
            a[j] = sp;
            rs += sp;
        }
        float inv = 0.9f / (rs + 1e-6f);
#pragma unroll
        for (int j = 0; j < 32; ++j) gA32[tid * 32 + j] = a[j] * inv;
    }
    for (int idx = tid; idx < 376; idx += blockDim.x) {
        int Ho = idx / 47, r = idx % 47;
        float s = 0.f;
#pragma unroll
        for (int h = 0; h < 8; ++h) s += WL[h * 8 + Ho] * rpb[h * 47 + r];
        gBmixr[idx] = s;
    }
    for (int idx = tid; idx < 768; idx += blockDim.x) {
        int o = idx / 24, l = idx % 24;
        float s = conv_b[o];
#pragma unroll
        for (int i = 0; i < 32; ++i)
            s += conv_w[(o * 32 + i) * 9 + 8] * pre_prompt[i * 24 + l];
        gPPC[idx] = s;
    }
    // packed qkv/m weights: idx = i4*128 + j*4 + d
    for (int idx = tid; idx < 1024; idx += blockDim.x) {
        int i4 = idx >> 7, j = (idx >> 2) & 31, d = idx & 3;
        int src = j * 32 + i4 * 4 + d;
        gWQKV4[idx]        = q_w[src];
        gWQKV4[1024 + idx] = k_w[src];
        gWQKV4[2048 + idx] = v_w[src];
        gWM4[idx]          = m_w[src];
    }
    // packed conv weights: idx = kt*1024 + i4*128 + o*4 + d
    for (int idx = tid; idx < 9216; idx += blockDim.x) {
        int kt = idx >> 10, i4 = (idx >> 7) & 7, o = (idx >> 2) & 31, d = idx & 3;
        gCWT2[idx] = conv_w[(o * 32 + i4 * 4 + d) * 9 + kt];
    }
}

// ---------------------------------------------------------------------------
// shared memory layout (floats)
// ---------------------------------------------------------------------------
#define S_FS    0                 // [216][36]
#define S_OVL   7776
// stats overlay:
#define S_PSUM  (S_OVL)           // [32][8]
#define S_PSQ   (S_OVL + 256)
#define S_AA    (S_OVL + 512)     // [32][33]
// attention overlay:
#define S_Q3    (S_OVL)           // [72][36]
#define S_K3    (S_OVL + 2592)
#define S_V3    (S_OVL + 5184)
#define S_SMX   (S_OVL + 7776)    // [8][676]
// conv overlay:
#define S_CW2   (S_OVL)           // 9216
#define S_PPC   (S_OVL + 9216)    // [32][25]
#define S_P1    (S_OVL + 10016)   // [32][25]
#define S_P2    (S_OVL + 10816)   // [32][25]
// fixed tail
#define S_WQKV4 20960             // 3072
#define S_WM4   24032             // 1024
#define S_BQ    25056
#define S_BK    25088
#define S_BV    25120
#define S_BM    25152
#define S_BMX   25184             // 376 pad 384
#define S_SDL   25568             // 32
#define S_VC1   25600
#define S_VC2   25632
#define S_VC3   25664
#define S_PBF   25696             // 32
#define S_PWT   25728             // [24][25]
#define S_SWL   26328             // 64
#define S_SWC   26392             // 64
#define S_TOTAL 26456

__global__ __launch_bounds__(NTHR, 2)
void prb_kernel(const float* __restrict__ x,
                const float* __restrict__ ln_g,  const float* __restrict__ ln_b,
                const float* __restrict__ rp_w1, const float* __restrict__ rp_b1,
                const float* __restrict__ rp_w2, const float* __restrict__ rp_b2,
                const float* __restrict__ mask_w, const float* __restrict__ mask_b,
                const float* __restrict__ val_w1, const float* __restrict__ val_b1,
                const float* __restrict__ val_w2, const float* __restrict__ val_b2,
                const float* __restrict__ fuse_gate,
                const float* __restrict__ q_b, const float* __restrict__ k_b,
                const float* __restrict__ v_b, const float* __restrict__ m_b,
                const float* __restrict__ W_logit, const float* __restrict__ W_ctx,
                const float* __restrict__ p_w,   const float* __restrict__ p_b,
                float* __restrict__ out)
{
    extern __shared__ float sm[];
    const int tid = threadIdx.x;
    const size_t base = (size_t)blockIdx.x * 6912;

    float* fs    = sm + S_FS;
    float* q3    = sm + S_Q3;
    float* k3    = sm + S_K3;
    float* v3    = sm + S_V3;
    float* smx   = sm + S_SMX;
    float* wqkv4 = sm + S_WQKV4;
    float* wm4   = sm + S_WM4;
    float* bq    = sm + S_BQ;
    float* bk    = sm + S_BK;
    float* bv    = sm + S_BV;
    float* bm    = sm + S_BM;
    float* sWL   = sm + S_SWL;
    float* sWC   = sm + S_SWC;
    float* bmx   = sm + S_BMX;
    float* sdl   = sm + S_SDL;
    float* vc1   = sm + S_VC1;
    float* vc2   = sm + S_VC2;
    float* vc3   = sm + S_VC3;
    float* pbf   = sm + S_PBF;
    float* pwT   = sm + S_PWT;
    float* aA    = sm + S_AA;
    float* psum  = sm + S_PSUM;
    float* psq   = sm + S_PSQ;
    float* cw2   = sm + S_CW2;
    float* ppc   = sm + S_PPC;
    float* p1    = sm + S_P1;
    float* p2    = sm + S_P2;

    const int j32 = tid & 31;
    const int g8  = tid >> 5;

    // ---------------- Phase 1: loads (conflict-free remap) ----------------
    for (int idx4 = tid; idx4 < 1728; idx4 += NTHR) {
        int c = idx4 & 31, g = idx4 >> 5;        // g in 0..53
        float4 v = *(const float4*)(x + base + c * 216 + g * 4);
        int row = g * 4;
        fs[(row + 0) * 36 + c] = v.x;
        fs[(row + 1) * 36 + c] = v.y;
        fs[(row + 2) * 36 + c] = v.z;
        fs[(row + 3) * 36 + c] = v.w;
    }
    for (int idx = tid; idx < 3072; idx += NTHR) wqkv4[idx] = gWQKV4[idx];
    for (int idx = tid; idx < 1024; idx += NTHR) {
        wm4[idx] = gWM4[idx];
        int j = idx >> 5, i = idx & 31;
        aA[j * 33 + i] = gA32[idx];
    }
    for (int idx = tid; idx < 576; idx += NTHR) {
        int lo = idx / 24, l = idx % 24;
        pwT[l * 25 + lo] = p_w[idx];
    }
    for (int idx = tid; idx < 376; idx += NTHR) bmx[idx] = gBmixr[idx];
    if (tid < 64) { sWL[tid] = W_logit[tid]; sWC[tid] = W_ctx[tid]; }
    if (tid < 32) {
        bq[tid] = q_b[tid]; bk[tid] = k_b[tid];
        bv[tid] = v_b[tid]; bm[tid] = m_b[tid];
    }
    if (tid < 24) pbf[tid] = p_b[tid];
    __syncthreads();

    // ---------------- Phase 2: per-channel stats (raw x) ----------------
    {
        int c = tid >> 3, part = tid & 7;
        float s = 0.f, sq = 0.f;
        int tl0 = part * 27;
#pragma unroll 9
        for (int k2 = 0; k2 < 27; ++k2) {
            float v = fs[(tl0 + k2) * 36 + c];
            s += v; sq += v * v;
        }
        psum[c * 8 + part] = s;
        psq [c * 8 + part] = sq;
    }
    __syncthreads();

    // ---------------- Phase 2b: warp-0 scalar chain ----------------
    if (tid < 32) {
        const int c = tid;
        float s = 0.f, sq = 0.f;
#pragma unroll
        for (int p = 0; p < 8; ++p) { s += psum[c * 8 + p]; sq += psq[c * 8 + p]; }
        float pooled = s * (1.f / 216.f);
        float varu = (sq - s * s * (1.f / 216.f)) * (1.f / 215.f);
        float scalec = fmaxf(sqrtf(fmaxf(varu, 0.f)), 1e-3f);

        float mu = pooled;
#pragma unroll
        for (int o = 16; o > 0; o >>= 1) mu += __shfl_xor_sync(0xffffffffu, mu, o);
        mu *= (1.f / 32.f);
        float d = pooled - mu;
        float var = d * d;
#pragma unroll
        for (int o = 16; o > 0; o >>= 1) var += __shfl_xor_sync(0xffffffffu, var, o);
        var *= (1.f / 32.f);
        float pn = d * rsqrtf(var + 1e-5f) * ln_g[c] + ln_b[c];
        vc1[c] = pn; __syncwarp();

        float acc = rp_b1[c];
#pragma unroll
        for (int i = 0; i < 32; ++i) acc += vc1[i] * rp_w1[c * 32 + i];
        vc2[c] = geluf(acc); __syncwarp();

        acc = rp_b2[c];
#pragma unroll
        for (int i = 0; i < 32; ++i) acc += vc2[i] * rp_w2[c * 32 + i];
        vc1[c] = acc; __syncwarp();       // pooled_rule

        acc = mask_b[c];
#pragma unroll
        for (int i = 0; i < 32; ++i) acc += vc1[i] * mask_w[c * 32 + i];
        float M = sigmoidf_(acc);

        acc = val_b1[c];
#pragma unroll
        for (int i = 0; i < 32; ++i) acc += vc1[i] * val_w1[c * 32 + i];
        vc2[c] = geluf(acc); __syncwarp();

        acc = val_b2[c];
#pragma unroll
        for (int i = 0; i < 32; ++i) acc += vc2[i] * val_w2[c * 32 + i];
        float v32 = tanhf(acc) * scalec + pooled;
        float xdo = (1.f - M) * pooled + M * v32;

        float y = xdo;
#pragma unroll
        for (int it = 0; it < 3; ++it) {
            vc3[c] = y; __syncwarp();
            float a2 = xdo;
#pragma unroll
            for (int j = 0; j < 32; ++j) a2 += vc3[j] * aA[c * 33 + j];
            y = a2;
            __syncwarp();
        }
        sdl[c] = sigmoidf_(fuse_gate[0]) * (y - pooled);
    }
    __syncthreads();

    // ---------------- Phase 4: attention, chunks of 3 contexts ----------------
    for (int tc = 0; tc < 3; ++tc) {
        const int rowbase = tc * 72;
        const int crow = g8 * 9;

        // 4a: qkv for 72 rows (9/thread-row-group), fuse folded, norm via shfl
        {
            float aq[9], ak[9], av[9];
#pragma unroll
            for (int r = 0; r < 9; ++r) { aq[r] = bq[j32]; ak[r] = bk[j32]; av[r] = bv[j32]; }
#pragma unroll
            for (int i4 = 0; i4 < 8; ++i4) {
                float4 sd4 = *(const float4*)&sdl[i4 * 4];
                float4 wq4 = *(const float4*)&wqkv4[(i4 * 32 + j32) * 4];
                float4 wk4 = *(const float4*)&wqkv4[1024 + (i4 * 32 + j32) * 4];
                float4 wv4 = *(const float4*)&wqkv4[2048 + (i4 * 32 + j32) * 4];
#pragma unroll
                for (int r = 0; r < 9; ++r) {
                    float4 f4 = *(const float4*)&fs[(rowbase + crow + r) * 36 + i4 * 4];
                    float f0 = f4.x + sd4.x, f1 = f4.y + sd4.y;
                    float f2 = f4.z + sd4.z, f3 = f4.w + sd4.w;
                    aq[r] = fmaf(f0, wq4.x, aq[r]); aq[r] = fmaf(f1, wq4.y, aq[r]);
                    aq[r] = fmaf(f2, wq4.z, aq[r]); aq[r] = fmaf(f3, wq4.w, aq[r]);
                    ak[r] = fmaf(f0, wk4.x, ak[r]); ak[r] = fmaf(f1, wk4.y, ak[r]);
                    ak[r] = fmaf(f2, wk4.z, ak[r]); ak[r] = fmaf(f3, wk4.w, ak[r]);
                    av[r] = fmaf(f0, wv4.x, av[r]); av[r] = fmaf(f1, wv4.y, av[r]);
                    av[r] = fmaf(f2, wv4.z, av[r]); av[r] = fmaf(f3, wv4.w, av[r]);
                }
            }
#pragma unroll
            for (int r = 0; r < 9; ++r) {
                float n2 = aq[r] * aq[r];
                n2 += __shfl_xor_sync(0xffffffffu, n2, 1);
                n2 += __shfl_xor_sync(0xffffffffu, n2, 2);
                aq[r] *= 0.5f / fmaxf(sqrtf(n2), 1e-12f);   // 1/sqrt(HD)=0.5 folded
                n2 = ak[r] * ak[r];
                n2 += __shfl_xor_sync(0xffffffffu, n2, 1);
                n2 += __shfl_xor_sync(0xffffffffu, n2, 2);
                ak[r] *= 1.f / fmaxf(sqrtf(n2), 1e-12f);
                n2 = av[r] * av[r];
                n2 += __shfl_xor_sync(0xffffffffu, n2, 1);
                n2 += __shfl_xor_sync(0xffffffffu, n2, 2);
                av[r] *= 1.f / fmaxf(sqrtf(n2), 1e-12f);
                q3[(crow + r) * 36 + j32] = aq[r];
                k3[(crow + r) * 36 + j32] = ak[r];
                v3[(crow + r) * 36 + j32] = av[r];
            }
        }
        __syncthreads();

        for (int t3 = 0; t3 < 3; ++t3) {
            const int ro = t3 * 24;

            // 4c: logits + W_logit mix (bias deferred to softmax)
            if (tid < 192) {
                const int i = tid >> 3, jg = tid & 7;
                float raw[3][8];
#pragma unroll
                for (int h = 0; h < 8; ++h) {
                    float4 qh = *(const float4*)&q3[(ro + i) * 36 + h * 4];
#pragma unroll
                    for (int r = 0; r < 3; ++r) {
                        float4 kv = *(const float4*)&k3[(ro + jg * 3 + r) * 36 + h * 4];
                        raw[r][h] = qh.x*kv.x + qh.y*kv.y + qh.z*kv.z + qh.w*kv.w;
                    }
                }
#pragma unroll
                for (int Ho = 0; Ho < 8; ++Ho) {
                    float wl[8];
#pragma unroll
                    for (int h = 0; h < 8; ++h) wl[h] = sWL[h * 8 + Ho];
#pragma unroll
                    for (int r = 0; r < 3; ++r) {
                        float acc = 0.f;
#pragma unroll
                        for (int h = 0; h < 8; ++h) acc = fmaf(raw[r][h], wl[h], acc);
                        smx[Ho * 676 + i * 28 + jg * 3 + r] = acc;
                    }
                }
            }
            __syncthreads();

            // 4d: softmax over j with rel-pos bias
            if (tid < 192) {
                const int Ho = tid / 24, i = tid % 24;
                float* row = &smx[Ho * 676 + i * 28];
                const float* brow = &bmx[Ho * 47 + i + 23];
                float e[24];
                {
                    const float4* rp = (const float4*)row;
#pragma unroll
                    for (int q4 = 0; q4 < 6; ++q4) {
                        float4 v4 = rp[q4];
                        e[q4*4+0] = v4.x; e[q4*4+1] = v4.y;
                        e[q4*4+2] = v4.z; e[q4*4+3] = v4.w;
                    }
                }
                float mx = -1e30f;
#pragma unroll
                for (int j = 0; j < 24; ++j) {
                    e[j] += brow[-j];
                    mx = fmaxf(mx, e[j]);
                }
                float ssum = 0.f;
#pragma unroll
                for (int j = 0; j < 24; ++j) { e[j] = __expf(e[j] - mx); ssum += e[j]; }
                float inv = 1.f / ssum;
                float4* wp = (float4*)row;
#pragma unroll
                for (int q4 = 0; q4 < 6; ++q4) {
                    float4 v4;
                    v4.x = e[q4*4+0] * inv; v4.y = e[q4*4+1] * inv;
                    v4.z = e[q4*4+2] * inv; v4.w = e[q4*4+3] * inv;
                    wp[q4] = v4;
                }
            }
            __syncthreads();

            // 4e: W_ctx mix, in place
            if (tid < 192) {
                const int i = tid >> 3, jg = tid & 7;
                float sv[3][8];
#pragma unroll
                for (int h = 0; h < 8; ++h)
#pragma unroll
                    for (int r = 0; r < 3; ++r)
                        sv[r][h] = smx[h * 676 + i * 28 + jg * 3 + r];
#pragma unroll
                for (int Ho = 0; Ho < 8; ++Ho) {
                    float wc[8];
#pragma unroll
                    for (int h = 0; h < 8; ++h) wc[h] = sWC[h * 8 + Ho];
#pragma unroll
                    for (int r = 0; r < 3; ++r) {
                        float acc = 0.f;
#pragma unroll
                        for (int h = 0; h < 8; ++h) acc = fmaf(sv[r][h], wc[h], acc);
                        smx[Ho * 676 + i * 28 + jg * 3 + r] = acc;
                    }
                }
            }
            __syncthreads();

            // 4f: AV -> att into q3 rows of this t3 (3 rows per warp-group)
            {
                const int h = j32 >> 2;
                float acc[3] = {0.f, 0.f, 0.f};
#pragma unroll
                for (int j4 = 0; j4 < 6; ++j4) {
                    float s4[3][4];
#pragma unroll
                    for (int r = 0; r < 3; ++r) {
                        float4 t = *(const float4*)&smx[h * 676 + (g8 * 3 + r) * 28 + j4 * 4];
                        s4[r][0] = t.x; s4[r][1] = t.y; s4[r][2] = t.z; s4[r][3] = t.w;
                    }
#pragma unroll
                    for (int s = 0; s < 4; ++s) {
                        float vv = v3[(ro + j4 * 4 + s) * 36 + j32];
#pragma unroll
                        for (int r = 0; r < 3; ++r)
                            acc[r] = fmaf(s4[r][s], vv, acc[r]);
                    }
                }
#pragma unroll
                for (int r = 0; r < 3; ++r)
                    q3[(ro + g8 * 3 + r) * 36 + j32] = acc[r];
            }
            __syncthreads();
        }

        // 4g: output projection for the whole chunk, overwrite fs rows
        {
            float am[9];
#pragma unroll
            for (int r = 0; r < 9; ++r) am[r] = bm[j32];
#pragma unroll
            for (int i4 = 0; i4 < 8; ++i4) {
                float4 wm_ = *(const float4*)&wm4[(i4 * 32 + j32) * 4];
#pragma unroll
                for (int r = 0; r < 9; ++r) {
                    float4 a4 = *(const float4*)&q3[(crow + r) * 36 + i4 * 4];
                    am[r] = fmaf(a4.x, wm_.x, am[r]); am[r] = fmaf(a4.y, wm_.y, am[r]);
                    am[r] = fmaf(a4.z, wm_.z, am[r]); am[r] = fmaf(a4.w, wm_.w, am[r]);
                }
            }
#pragma unroll
            for (int r = 0; r < 9; ++r)
                fs[(rowbase + crow + r) * 36 + j32] = am[r];
        }
        __syncthreads();
    }

    // ---------------- Phase 5: conv over contexts (all 256 threads) --------
    for (int idx = tid; idx < 9216; idx += NTHR) cw2[idx] = gCWT2[idx];
    for (int idx = tid; idx < 768; idx += NTHR) {
        int o = idx / 24, l = idx % 24;
        ppc[o * 25 + l] = gPPC[idx];
    }
    __syncthreads();
    {
        const int lbase = g8 * 3;
        float acc[3];
#pragma unroll
        for (int r = 0; r < 3; ++r) acc[r] = ppc[j32 * 25 + lbase + r];
#pragma unroll
        for (int kt = 0; kt < 8; ++kt) {
#pragma unroll
            for (int i4 = 0; i4 < 8; ++i4) {
                float4 w4 = *(const float4*)&cw2[((kt * 8 + i4) * 32 + j32) * 4];
#pragma unroll
                for (int r = 0; r < 3; ++r) {
                    float4 f4 = *(const float4*)&fs[(kt * 24 + lbase + r) * 36 + i4 * 4];
                    acc[r] = fmaf(f4.x, w4.x, acc[r]);
                    acc[r] = fmaf(f4.y, w4.y, acc[r]);
                    acc[r] = fmaf(f4.z, w4.z, acc[r]);
                    acc[r] = fmaf(f4.w, w4.w, acc[r]);
                }
            }
        }
#pragma unroll
        for (int r = 0; r < 3; ++r)
            p1[j32 * 25 + lbase + r] = fmaxf(acc[r], 0.f);
    }
    __syncthreads();

    // ---------------- Phase 6: token linear ----------------
    for (int idx = tid; idx < 768; idx += NTHR) {
        int o = idx / 24, lo = idx % 24;
        float acc = pbf[lo];
#pragma unroll
        for (int l = 0; l < 24; ++l)
            acc = fmaf(p1[o * 25 + l], pwT[l * 25 + lo], acc);
        p2[o * 25 + lo] = acc;
    }
    __syncthreads();

    // ---------------- Phase 7: output (conflict-free remap) ----------------
    for (int idx4 = tid; idx4 < 1728; idx4 += NTHR) {
        int c = idx4 & 31, g = idx4 >> 5;
        int tl = g * 4;
        float4 v;
        v.x = fs[(tl + 0) * 36 + c];
        v.y = fs[(tl + 1) * 36 + c];
        v.z = fs[(tl + 2) * 36 + c];
        v.w = fs[(tl + 3) * 36 + c];
        if (g >= 48) {
            v.x -= p2[c * 25 + (tl - 192)];
            v.y -= p2[c * 25 + (tl - 191)];
            v.z -= p2[c * 25 + (tl - 190)];
            v.w -= p2[c * 25 + (tl - 189)];
        }
        *(float4*)(out + base + c * 216 + tl) = v;
    }
}

extern "C" void kernel_launch(void* const* d_in, const int* in_sizes, int n_in,
                              void* d_out, int out_size) {
    const float* x        = (const float*)d_in[0];
    const float* ln_g     = (const float*)d_in[1];
    const float* ln_b     = (const float*)d_in[2];
    const float* rp_w1    = (const float*)d_in[3];
    const float* rp_b1    = (const float*)d_in[4];
    const float* rp_w2    = (const float*)d_in[5];
    const float* rp_b2    = (const float*)d_in[6];
    const float* W_causal = (const float*)d_in[7];
    const float* mask_w   = (const float*)d_in[8];
    const float* mask_b   = (const float*)d_in[9];
    const float* val_w1   = (const float*)d_in[10];
    const float* val_b1   = (const float*)d_in[11];
    const float* val_w2   = (const float*)d_in[12];
    const float* val_b2   = (const float*)d_in[13];
    const float* fuse_g   = (const float*)d_in[14];
    const float* q_w      = (const float*)d_in[15];
    const float* q_b      = (const float*)d_in[16];
    const float* k_w      = (const float*)d_in[17];
    const float* k_b      = (const float*)d_in[18];
    const float* v_w      = (const float*)d_in[19];
    const float* v_b      = (const float*)d_in[20];
    const float* m_w      = (const float*)d_in[21];
    const float* m_b      = (const float*)d_in[22];
    const float* W_logit  = (const float*)d_in[23];
    const float* W_ctx    = (const float*)d_in[24];
    const float* rpb      = (const float*)d_in[25];
    const float* pre_p    = (const float*)d_in[26];
    const float* conv_w   = (const float*)d_in[27];
    const float* conv_b   = (const float*)d_in[28];
    const float* p_w      = (const float*)d_in[29];
    const float* p_b      = (const float*)d_in[30];
    float* out = (float*)d_out;

    const int smem_bytes = S_TOTAL * 4;
    cudaFuncSetAttribute(prb_kernel, cudaFuncAttributeMaxDynamicSharedMemorySize,
                         smem_bytes);

    prb_precompute<<<1, 256>>>(W_causal, W_logit, rpb, conv_w, conv_b, pre_p,
                               q_w, k_w, v_w, m_w);

    int B = in_sizes[0] / 6912;
    prb_kernel<<<B, NTHR, smem_bytes>>>(
        x, ln_g, ln_b, rp_w1, rp_b1, rp_w2, rp_b2,
        mask_w, mask_b, val_w1, val_b1, val_w2, val_b2, fuse_g,
        q_b, k_b, v_b, m_b, W_logit, W_ctx, p_w, p_b, out);
}

// round 14
// speedup vs baseline: 1.1602x; 1.0136x over previous
#include <cuda_runtime.h>
#include <cuda_bf16.h>
#include <math.h>

// ============================================================================
// PredictiveReasoningBlock fused monolith, one CTA per batch element.
// Round 13: smem diet -> 3 CTAs/SM. x streamed per-t (double-buffered 24-row
// transpose, prefetched by warps 6-7), weights from L1-resident global,
// dedicated xatt tile for conv/output. Arithmetic identical to R12.
// Shapes: B=4096, D=32, T=9, L=24, H=8, HD=4.
// ============================================================================

#define NTHR 256

__device__ float gA32[1024];     // 0.9*softplus(W_causal)*(1-I), row-normalized
__device__ float gBmixr[376];    // sum_h W_logit[h,Ho]*rel_pos_bias[h,r] (8x47)
__device__ float gPPC[768];      // conv_b[o] + sum_i conv_w[o,i,8]*pre_prompt[i,l]
__device__ float gWQKV4[3072];   // [m][i4][lane][4]: W_m[lane][i4*4+d]
__device__ float gWM4[1024];     // [i4][lane][4]
__device__ float gCWT2[9216];    // [kt][i4][o][4] = conv_w[o][i4*4+d][kt]

__device__ __forceinline__ float geluf(float x) {
    return 0.5f * x * (1.0f + erff(x * 0.7071067811865476f));
}
__device__ __forceinline__ float sigmoidf_(float x) {
    return 1.0f / (1.0f + __expf(-x));
}

__global__ void prb_precompute(const float* __restrict__ Wc,
                               const float* __restrict__ WL,
                               const float* __restrict__ rpb,
                               const float* __restrict__ conv_w,
                               const float* __restrict__ conv_b,
                               const float* __restrict__ pre_prompt,
                               const float* __restrict__ q_w,
                               const float* __restrict__ k_w,
                               const float* __restrict__ v_w,
                               const float* __restrict__ m_w) {
    int tid = threadIdx.x;
    if (tid < 32) {
        float a[32];
        float rs = 0.f;
#pragma unroll
        for (int j = 0; j < 32; ++j) {
            float w = Wc[tid * 32 + j];
            float sp = (w > 20.f) ? w : log1pf(expf(w));
            if (j == tid) sp = 0.f;
            a[j] = sp;
            rs += sp;
        }
        float inv = 0.9f / (rs + 1e-6f);
#pragma unroll
        for (int j = 0; j < 32; ++j) gA32[tid * 32 + j] = a[j] * inv;
    }
    for (int idx = tid; idx < 376; idx += blockDim.x) {
        int Ho = idx / 47, r = idx % 47;
        float s = 0.f;
#pragma unroll
        for (int h = 0; h < 8; ++h) s += WL[h * 8 + Ho] * rpb[h * 47 + r];
        gBmixr[idx] = s;
    }
    for (int idx = tid; idx < 768; idx += blockDim.x) {
        int o = idx / 24, l = idx % 24;
        float s = conv_b[o];
#pragma unroll
        for (int i = 0; i < 32; ++i)
            s += conv_w[(o * 32 + i) * 9 + 8] * pre_prompt[i * 24 + l];
        gPPC[idx] = s;
    }
    for (int idx = tid; idx < 1024; idx += blockDim.x) {
        int i4 = idx >> 7, j = (idx >> 2) & 31, d = idx & 3;
        int src = j * 32 + i4 * 4 + d;
        gWQKV4[idx]        = q_w[src];
        gWQKV4[1024 + idx] = k_w[src];
        gWQKV4[2048 + idx] = v_w[src];
        gWM4[idx]          = m_w[src];
    }
    for (int idx = tid; idx < 9216; idx += blockDim.x) {
        int kt = idx >> 10, i4 = (idx >> 7) & 7, o = (idx >> 2) & 31, d = idx & 3;
        gCWT2[idx] = conv_w[(o * 32 + i4 * 4 + d) * 9 + kt];
    }
}

// ---------------------------------------------------------------------------
// shared memory layout (floats), total 18904 = 75.6 KB -> 3 CTAs/SM
// ---------------------------------------------------------------------------
#define S_XATT  0                 // [216][36] x_att accumulation tile
#define S_W     7776              // working region (9728)
#define S_XB0   (S_W)             // [24][36]
#define S_XB1   (S_W + 864)
#define S_Q3    (S_W + 1728)      // [24][36]
#define S_K3    (S_W + 2592)
#define S_V3    (S_W + 3456)
#define S_SMX   (S_W + 4320)      // [8][676]
// stats overlay (inside SMX region; done before any smx use)
#define S_PSUM  (S_SMX)           // [32][8]
#define S_PSQ   (S_SMX + 256)
#define S_AA    (S_SMX + 512)     // [32][33]
// conv overlay (inside W after attention)
#define S_PPC   (S_W)             // [32][25]
#define S_P1    (S_W + 800)
#define S_P2    (S_W + 1600)
// fixed tail
#define S_BQ    17504
#define S_BK    17536
#define S_BV    17568
#define S_BM    17600
#define S_BMX   17632             // 376 pad 384
#define S_SDL   18016             // 32 (16B aligned)
#define S_VC1   18048
#define S_VC2   18080
#define S_VC3   18112
#define S_PBF   18144
#define S_PWT   18176             // [24][25]
#define S_SWL   18776             // 64
#define S_SWC   18840             // 64
#define S_TOTAL 18904

__global__ __launch_bounds__(NTHR, 3)
void prb_kernel(const float* __restrict__ x,
                const float* __restrict__ ln_g,  const float* __restrict__ ln_b,
                const float* __restrict__ rp_w1, const float* __restrict__ rp_b1,
                const float* __restrict__ rp_w2, const float* __restrict__ rp_b2,
                const float* __restrict__ mask_w, const float* __restrict__ mask_b,
                const float* __restrict__ val_w1, const float* __restrict__ val_b1,
                const float* __restrict__ val_w2, const float* __restrict__ val_b2,
                const float* __restrict__ fuse_gate,
                const float* __restrict__ q_b, const float* __restrict__ k_b,
                const float* __restrict__ v_b, const float* __restrict__ m_b,
                const float* __restrict__ W_logit, const float* __restrict__ W_ctx,
                const float* __restrict__ p_w,   const float* __restrict__ p_b,
                float* __restrict__ out)
{
    extern __shared__ float sm[];
    const int tid = threadIdx.x;
    const size_t base = (size_t)blockIdx.x * 6912;

    float* xatt = sm + S_XATT;
    float* q3   = sm + S_Q3;
    float* k3   = sm + S_K3;
    float* v3   = sm + S_V3;
    float* smx  = sm + S_SMX;
    float* bq   = sm + S_BQ;
    float* bk   = sm + S_BK;
    float* bv   = sm + S_BV;
    float* bm   = sm + S_BM;
    float* sWL  = sm + S_SWL;
    float* sWC  = sm + S_SWC;
    float* bmx  = sm + S_BMX;
    float* sdl  = sm + S_SDL;
    float* vc1  = sm + S_VC1;
    float* vc2  = sm + S_VC2;
    float* vc3  = sm + S_VC3;
    float* pbf  = sm + S_PBF;
    float* pwT  = sm + S_PWT;
    float* aA   = sm + S_AA;
    float* psum = sm + S_PSUM;
    float* psq  = sm + S_PSQ;
    float* ppc  = sm + S_PPC;
    float* p1   = sm + S_P1;
    float* p2   = sm + S_P2;

    const int j32 = tid & 31;
    const int g8  = tid >> 5;

    // ---------------- Phase 1: stage small tables + stats partials --------
    for (int idx = tid; idx < 1024; idx += NTHR) {
        int j = idx >> 5, i = idx & 31;
        aA[j * 33 + i] = gA32[idx];
    }
    for (int idx = tid; idx < 576; idx += NTHR) {
        int lo = idx / 24, l = idx % 24;
        pwT[l * 25 + lo] = p_w[idx];
    }
    for (int idx = tid; idx < 376; idx += NTHR) bmx[idx] = gBmixr[idx];
    if (tid < 64) { sWL[tid] = W_logit[tid]; sWC[tid] = W_ctx[tid]; }
    if (tid < 32) {
        bq[tid] = q_b[tid]; bk[tid] = k_b[tid];
        bv[tid] = v_b[tid]; bm[tid] = m_b[tid];
    }
    if (tid < 24) pbf[tid] = p_b[tid];
    // prefetch t=0 rows into XB0
    if (tid < 192) {
        int c = tid & 31, g = tid >> 5;            // g in 0..5
        float4 v = *(const float4*)(x + base + c * 216 + g * 4);
        float* xb = sm + S_XB0;
        int row = g * 4;
        xb[(row + 0) * 36 + c] = v.x;
        xb[(row + 1) * 36 + c] = v.y;
        xb[(row + 2) * 36 + c] = v.z;
        xb[(row + 3) * 36 + c] = v.w;
    }
    // stats partials straight from GMEM
    {
        int c = tid >> 3, part = tid & 7;
        const float* xp = x + base + c * 216 + part * 27;
        float s = 0.f, sq = 0.f;
#pragma unroll 9
        for (int k2 = 0; k2 < 27; ++k2) {
            float v = xp[k2];
            s += v; sq += v * v;
        }
        psum[c * 8 + part] = s;
        psq [c * 8 + part] = sq;
    }
    __syncthreads();

    // ---------------- Phase 2b: warp-0 scalar chain ----------------
    if (tid < 32) {
        const int c = tid;
        float s = 0.f, sq = 0.f;
#pragma unroll
        for (int p = 0; p < 8; ++p) { s += psum[c * 8 + p]; sq += psq[c * 8 + p]; }
        float pooled = s * (1.f / 216.f);
        float varu = (sq - s * s * (1.f / 216.f)) * (1.f / 215.f);
        float scalec = fmaxf(sqrtf(fmaxf(varu, 0.f)), 1e-3f);

        float mu = pooled;
#pragma unroll
        for (int o = 16; o > 0; o >>= 1) mu += __shfl_xor_sync(0xffffffffu, mu, o);
        mu *= (1.f / 32.f);
        float d = pooled - mu;
        float var = d * d;
#pragma unroll
        for (int o = 16; o > 0; o >>= 1) var += __shfl_xor_sync(0xffffffffu, var, o);
        var *= (1.f / 32.f);
        float pn = d * rsqrtf(var + 1e-5f) * ln_g[c] + ln_b[c];
        vc1[c] = pn; __syncwarp();

        float acc = rp_b1[c];
#pragma unroll
        for (int i = 0; i < 32; ++i) acc += vc1[i] * rp_w1[c * 32 + i];
        vc2[c] = geluf(acc); __syncwarp();

        acc = rp_b2[c];
#pragma unroll
        for (int i = 0; i < 32; ++i) acc += vc2[i] * rp_w2[c * 32 + i];
        vc1[c] = acc; __syncwarp();       // pooled_rule

        acc = mask_b[c];
#pragma unroll
        for (int i = 0; i < 32; ++i) acc += vc1[i] * mask_w[c * 32 + i];
        float M = sigmoidf_(acc);

        acc = val_b1[c];
#pragma unroll
        for (int i = 0; i < 32; ++i) acc += vc1[i] * val_w1[c * 32 + i];
        vc2[c] = geluf(acc); __syncwarp();

        acc = val_b2[c];
#pragma unroll
        for (int i = 0; i < 32; ++i) acc += vc2[i] * val_w2[c * 32 + i];
        float v32 = tanhf(acc) * scalec + pooled;
        float xdo = (1.f - M) * pooled + M * v32;

        float y = xdo;
#pragma unroll
        for (int it = 0; it < 3; ++it) {
            vc3[c] = y; __syncwarp();
            float a2 = xdo;
#pragma unroll
            for (int j = 0; j < 32; ++j) a2 += vc3[j] * aA[c * 33 + j];
            y = a2;
            __syncwarp();
        }
        sdl[c] = sigmoidf_(fuse_gate[0]) * (y - pooled);
    }
    __syncthreads();

    // ---------------- Phase 4: attention per context t ----------------
    for (int t = 0; t < 9; ++t) {
        float* xb = sm + ((t & 1) ? S_XB1 : S_XB0);
        float* xn = sm + ((t & 1) ? S_XB0 : S_XB1);

        // 4a: qkv projection (3 rows per thread-group), fuse add, norm shfl
        {
            float aq[3], ak[3], av[3];
#pragma unroll
            for (int r = 0; r < 3; ++r) { aq[r] = bq[j32]; ak[r] = bk[j32]; av[r] = bv[j32]; }
#pragma unroll
            for (int i4 = 0; i4 < 8; ++i4) {
                float4 sd4 = *(const float4*)&sdl[i4 * 4];
                float4 wq4 = *(const float4*)&gWQKV4[(i4 * 32 + j32) * 4];
                float4 wk4 = *(const float4*)&gWQKV4[1024 + (i4 * 32 + j32) * 4];
                float4 wv4 = *(const float4*)&gWQKV4[2048 + (i4 * 32 + j32) * 4];
#pragma unroll
                for (int r = 0; r < 3; ++r) {
                    float4 f4 = *(const float4*)&xb[(g8 * 3 + r) * 36 + i4 * 4];
                    float f0 = f4.x + sd4.x, f1 = f4.y + sd4.y;
                    float f2 = f4.z + sd4.z, f3 = f4.w + sd4.w;
                    aq[r] = fmaf(f0, wq4.x, aq[r]); aq[r] = fmaf(f1, wq4.y, aq[r]);
                    aq[r] = fmaf(f2, wq4.z, aq[r]); aq[r] = fmaf(f3, wq4.w, aq[r]);
                    ak[r] = fmaf(f0, wk4.x, ak[r]); ak[r] = fmaf(f1, wk4.y, ak[r]);
                    ak[r] = fmaf(f2, wk4.z, ak[r]); ak[r] = fmaf(f3, wk4.w, ak[r]);
                    av[r] = fmaf(f0, wv4.x, av[r]); av[r] = fmaf(f1, wv4.y, av[r]);
                    av[r] = fmaf(f2, wv4.z, av[r]); av[r] = fmaf(f3, wv4.w, av[r]);
                }
            }
#pragma unroll
            for (int r = 0; r < 3; ++r) {
                float n2 = aq[r] * aq[r];
                n2 += __shfl_xor_sync(0xffffffffu, n2, 1);
                n2 += __shfl_xor_sync(0xffffffffu, n2, 2);
                aq[r] *= 0.5f / fmaxf(sqrtf(n2), 1e-12f);   // 1/sqrt(HD)=0.5 folded
                n2 = ak[r] * ak[r];
                n2 += __shfl_xor_sync(0xffffffffu, n2, 1);
                n2 += __shfl_xor_sync(0xffffffffu, n2, 2);
                ak[r] *= 1.f / fmaxf(sqrtf(n2), 1e-12f);
                n2 = av[r] * av[r];
                n2 += __shfl_xor_sync(0xffffffffu, n2, 1);
                n2 += __shfl_xor_sync(0xffffffffu, n2, 2);
                av[r] *= 1.f / fmaxf(sqrtf(n2), 1e-12f);
                q3[(g8 * 3 + r) * 36 + j32] = aq[r];
                k3[(g8 * 3 + r) * 36 + j32] = ak[r];
                v3[(g8 * 3 + r) * 36 + j32] = av[r];
            }
        }
        __syncthreads();

        // 4c (warps 0-5) + prefetch next t (warps 6-7)
        if (tid < 192) {
            const int i = tid >> 3, jg = tid & 7;
            float raw[3][8];
#pragma unroll
            for (int h = 0; h < 8; ++h) {
                float4 qh = *(const float4*)&q3[i * 36 + h * 4];
#pragma unroll
                for (int r = 0; r < 3; ++r) {
                    float4 kv = *(const float4*)&k3[(jg * 3 + r) * 36 + h * 4];
                    raw[r][h] = qh.x*kv.x + qh.y*kv.y + qh.z*kv.z + qh.w*kv.w;
                }
            }
#pragma unroll
            for (int Ho = 0; Ho < 8; ++Ho) {
                float wl[8];
#pragma unroll
                for (int h = 0; h < 8; ++h) wl[h] = sWL[h * 8 + Ho];
#pragma unroll
                for (int r = 0; r < 3; ++r) {
                    float acc = 0.f;
#pragma unroll
                    for (int h = 0; h < 8; ++h) acc = fmaf(raw[r][h], wl[h], acc);
                    smx[Ho * 676 + i * 28 + jg * 3 + r] = acc;
                }
            }
        } else if (t < 8) {
            // 64 threads load next t's 24 rows (192 float4s, 3 each)
            int lt = tid - 192;
#pragma unroll
            for (int k = 0; k < 3; ++k) {
                int idx4 = lt + k * 64;
                int c = idx4 & 31, g = idx4 >> 5;
                float4 v = *(const float4*)(x + base + c * 216 + (t + 1) * 24 + g * 4);
                int row = g * 4;
                xn[(row + 0) * 36 + c] = v.x;
                xn[(row + 1) * 36 + c] = v.y;
                xn[(row + 2) * 36 + c] = v.z;
                xn[(row + 3) * 36 + c] = v.w;
            }
        }
        __syncthreads();

        // 4d: softmax over j with rel-pos bias
        if (tid < 192) {
            const int Ho = tid / 24, i = tid % 24;
            float* row = &smx[Ho * 676 + i * 28];
            const float* brow = &bmx[Ho * 47 + i + 23];
            float e[24];
            {
                const float4* rp = (const float4*)row;
#pragma unroll
                for (int q4 = 0; q4 < 6; ++q4) {
                    float4 v4 = rp[q4];
                    e[q4*4+0] = v4.x; e[q4*4+1] = v4.y;
                    e[q4*4+2] = v4.z; e[q4*4+3] = v4.w;
                }
            }
            float mx = -1e30f;
#pragma unroll
            for (int j = 0; j < 24; ++j) {
                e[j] += brow[-j];
                mx = fmaxf(mx, e[j]);
            }
            float ssum = 0.f;
#pragma unroll
            for (int j = 0; j < 24; ++j) { e[j] = __expf(e[j] - mx); ssum += e[j]; }
            float inv = 1.f / ssum;
            float4* wp = (float4*)row;
#pragma unroll
            for (int q4 = 0; q4 < 6; ++q4) {
                float4 v4;
                v4.x = e[q4*4+0] * inv; v4.y = e[q4*4+1] * inv;
                v4.z = e[q4*4+2] * inv; v4.w = e[q4*4+3] * inv;
                wp[q4] = v4;
            }
        }
        __syncthreads();

        // 4e: W_ctx mix, in place
        if (tid < 192) {
            const int i = tid >> 3, jg = tid & 7;
            float sv[3][8];
#pragma unroll
            for (int h = 0; h < 8; ++h)
#pragma unroll
                for (int r = 0; r < 3; ++r)
                    sv[r][h] = smx[h * 676 + i * 28 + jg * 3 + r];
#pragma unroll
            for (int Ho = 0; Ho < 8; ++Ho) {
                float wc[8];
#pragma unroll
                for (int h = 0; h < 8; ++h) wc[h] = sWC[h * 8 + Ho];
#pragma unroll
                for (int r = 0; r < 3; ++r) {
                    float acc = 0.f;
#pragma unroll
                    for (int h = 0; h < 8; ++h) acc = fmaf(sv[r][h], wc[h], acc);
                    smx[Ho * 676 + i * 28 + jg * 3 + r] = acc;
                }
            }
        }
        __syncthreads();

        // 4f: AV -> att into q3 (3 rows per thread-group)
        {
            const int h = j32 >> 2;
            float acc[3] = {0.f, 0.f, 0.f};
#pragma unroll
            for (int j4 = 0; j4 < 6; ++j4) {
                float s4[3][4];
#pragma unroll
                for (int r = 0; r < 3; ++r) {
                    float4 tv = *(const float4*)&smx[h * 676 + (g8 * 3 + r) * 28 + j4 * 4];
                    s4[r][0] = tv.x; s4[r][1] = tv.y; s4[r][2] = tv.z; s4[r][3] = tv.w;
                }
#pragma unroll
                for (int s = 0; s < 4; ++s) {
                    float vv = v3[(j4 * 4 + s) * 36 + j32];
#pragma unroll
                    for (int r = 0; r < 3; ++r)
                        acc[r] = fmaf(s4[r][s], vv, acc[r]);
                }
            }
#pragma unroll
            for (int r = 0; r < 3; ++r)
                q3[(g8 * 3 + r) * 36 + j32] = acc[r];
        }
        __syncthreads();

        // 4g: output projection -> xatt rows of this t
        {
            float am[3];
#pragma unroll
            for (int r = 0; r < 3; ++r) am[r] = bm[j32];
#pragma unroll
            for (int i4 = 0; i4 < 8; ++i4) {
                float4 wm_ = *(const float4*)&gWM4[(i4 * 32 + j32) * 4];
#pragma unroll
                for (int r = 0; r < 3; ++r) {
                    float4 a4 = *(const float4*)&q3[(g8 * 3 + r) * 36 + i4 * 4];
                    am[r] = fmaf(a4.x, wm_.x, am[r]); am[r] = fmaf(a4.y, wm_.y, am[r]);
                    am[r] = fmaf(a4.z, wm_.z, am[r]); am[r] = fmaf(a4.w, wm_.w, am[r]);
                }
            }
#pragma unroll
            for (int r = 0; r < 3; ++r)
                xatt[(t * 24 + g8 * 3 + r) * 36 + j32] = am[r];
        }
        __syncthreads();
    }

    // ---------------- Phase 5: conv over contexts (all 256 threads) --------
    for (int idx = tid; idx < 768; idx += NTHR) {
        int o = idx / 24, l = idx % 24;
        ppc[o * 25 + l] = gPPC[idx];
    }
    __syncthreads();
    {
        const int lbase = g8 * 3;
        float acc[3];
#pragma unroll
        for (int r = 0; r < 3; ++r) acc[r] = ppc[j32 * 25 + lbase + r];
#pragma unroll
        for (int kt = 0; kt < 8; ++kt) {
#pragma unroll
            for (int i4 = 0; i4 < 8; ++i4) {
                float4 w4 = *(const float4*)&gCWT2[((kt * 8 + i4) * 32 + j32) * 4];
#pragma unroll
                for (int r = 0; r < 3; ++r) {
                    float4 f4 = *(const float4*)&xatt[(kt * 24 + lbase + r) * 36 + i4 * 4];
                    acc[r] = fmaf(f4.x, w4.x, acc[r]);
                    acc[r] = fmaf(f4.y, w4.y, acc[r]);
                    acc[r] = fmaf(f4.z, w4.z, acc[r]);
                    acc[r] = fmaf(f4.w, w4.w, acc[r]);
                }
            }
        }
#pragma unroll
        for (int r = 0; r < 3; ++r)
            p1[j32 * 25 + lbase + r] = fmaxf(acc[r], 0.f);
    }
    __syncthreads();

    // ---------------- Phase 6: token linear ----------------
    for (int idx = tid; idx < 768; idx += NTHR) {
        int o = idx / 24, lo = idx % 24;
        float acc = pbf[lo];
#pragma unroll
        for (int l = 0; l < 24; ++l)
            acc = fmaf(p1[o * 25 + l], pwT[l * 25 + lo], acc);
        p2[o * 25 + lo] = acc;
    }
    __syncthreads();

    // ---------------- Phase 7: output (conflict-free remap) ----------------
    for (int idx4 = tid; idx4 < 1728; idx4 += NTHR) {
        int c = idx4 & 31, g = idx4 >> 5;
        int tl = g * 4;
        float4 v;
        v.x = xatt[(tl + 0) * 36 + c];
        v.y = xatt[(tl + 1) * 36 + c];
        v.z = xatt[(tl + 2) * 36 + c];
        v.w = xatt[(tl + 3) * 36 + c];
        if (g >= 48) {
            v.x -= p2[c * 25 + (tl - 192)];
            v.y -= p2[c * 25 + (tl - 191)];
            v.z -= p2[c * 25 + (tl - 190)];
            v.w -= p2[c * 25 + (tl - 189)];
        }
        *(float4*)(out + base + c * 216 + tl) = v;
    }
}

extern "C" void kernel_launch(void* const* d_in, const int* in_sizes, int n_in,
                              void* d_out, int out_size) {
    const float* x        = (const float*)d_in[0];
    const float* ln_g     = (const float*)d_in[1];
    const float* ln_b     = (const float*)d_in[2];
    const float* rp_w1    = (const float*)d_in[3];
    const float* rp_b1    = (const float*)d_in[4];
    const float* rp_w2    = (const float*)d_in[5];
    const float* rp_b2    = (const float*)d_in[6];
    const float* W_causal = (const float*)d_in[7];
    const float* mask_w   = (const float*)d_in[8];
    const float* mask_b   = (const float*)d_in[9];
    const float* val_w1   = (const float*)d_in[10];
    const float* val_b1   = (const float*)d_in[11];
    const float* val_w2   = (const float*)d_in[12];
    const float* val_b2   = (const float*)d_in[13];
    const float* fuse_g   = (const float*)d_in[14];
    const float* q_w      = (const float*)d_in[15];
    const float* q_b      = (const float*)d_in[16];
    const float* k_w      = (const float*)d_in[17];
    const float* k_b      = (const float*)d_in[18];
    const float* v_w      = (const float*)d_in[19];
    const float* v_b      = (const float*)d_in[20];
    const float* m_w      = (const float*)d_in[21];
    const float* m_b      = (const float*)d_in[22];
    const float* W_logit  = (const float*)d_in[23];
    const float* W_ctx    = (const float*)d_in[24];
    const float* rpb      = (const float*)d_in[25];
    const float* pre_p    = (const float*)d_in[26];
    const float* conv_w   = (const float*)d_in[27];
    const float* conv_b   = (const float*)d_in[28];
    const float* p_w      = (const float*)d_in[29];
    const float* p_b      = (const float*)d_in[30];
    float* out = (float*)d_out;

    const int smem_bytes = S_TOTAL * 4;
    cudaFuncSetAttribute(prb_kernel, cudaFuncAttributeMaxDynamicSharedMemorySize,
                         smem_bytes);

    prb_precompute<<<1, 256>>>(W_causal, W_logit, rpb, conv_w, conv_b, pre_p,
                               q_w, k_w, v_w, m_w);

    int B = in_sizes[0] / 6912;
    prb_kernel<<<B, NTHR, smem_bytes>>>(
        x, ln_g, ln_b, rp_w1, rp_b1, rp_w2, rp_b2,
        mask_w, mask_b, val_w1, val_b1, val_w2, val_b2, fuse_g,
        q_b, k_b, v_b, m_b, W_logit, W_ctx, p_w, p_b, out);
}

// round 15
// speedup vs baseline: 1.1654x; 1.0045x over previous
#include <cuda_runtime.h>
#include <cuda_bf16.h>
#include <math.h>

// ============================================================================
// PredictiveReasoningBlock fused monolith, one CTA per batch element.
// Round 14: R13 (3 CTAs/SM, streamed x, global weights) + merged register/shfl
// logits->softmax->W_ctx phase (R7) now that L1 is the binding constraint.
// Shapes: B=4096, D=32, T=9, L=24, H=8, HD=4.
// ============================================================================

#define NTHR 256

__device__ float gA32[1024];     // 0.9*softplus(W_causal)*(1-I), row-normalized
__device__ float gBmixr[376];    // sum_h W_logit[h,Ho]*rel_pos_bias[h,r] (8x47)
__device__ float gPPC[768];      // conv_b[o] + sum_i conv_w[o,i,8]*pre_prompt[i,l]
__device__ float gWQKV4[3072];   // [m][i4][lane][4]: W_m[lane][i4*4+d]
__device__ float gWM4[1024];     // [i4][lane][4]
__device__ float gCWT2[9216];    // [kt][i4][o][4] = conv_w[o][i4*4+d][kt]

__device__ __forceinline__ float geluf(float x) {
    return 0.5f * x * (1.0f + erff(x * 0.7071067811865476f));
}
__device__ __forceinline__ float sigmoidf_(float x) {
    return 1.0f / (1.0f + __expf(-x));
}

__global__ void prb_precompute(const float* __restrict__ Wc,
                               const float* __restrict__ WL,
                               const float* __restrict__ rpb,
                               const float* __restrict__ conv_w,
                               const float* __restrict__ conv_b,
                               const float* __restrict__ pre_prompt,
                               const float* __restrict__ q_w,
                               const float* __restrict__ k_w,
                               const float* __restrict__ v_w,
                               const float* __restrict__ m_w) {
    int tid = threadIdx.x;
    if (tid < 32) {
        float a[32];
        float rs = 0.f;
#pragma unroll
        for (int j = 0; j < 32; ++j) {
            float w = Wc[tid * 32 + j];
            float sp = (w > 20.f) ? w : log1pf(expf(w));
            if (j == tid) sp = 0.f;
            a[j] = sp;
            rs += sp;
        }
        float inv = 0.9f / (rs + 1e-6f);
#pragma unroll
        for (int j = 0; j < 32; ++j) gA32[tid * 32 + j] = a[j] * inv;
    }
    for (int idx = tid; idx < 376; idx += blockDim.x) {
        int Ho = idx / 47, r = idx % 47;
        float s = 0.f;
#pragma unroll
        for (int h = 0; h < 8; ++h) s += WL[h * 8 + Ho] * rpb[h * 47 + r];
        gBmixr[idx] = s;
    }
    for (int idx = tid; idx < 768; idx += blockDim.x) {
        int o = idx / 24, l = idx % 24;
        float s = conv_b[o];
#pragma unroll
        for (int i = 0; i < 32; ++i)
            s += conv_w[(o * 32 + i) * 9 + 8] * pre_prompt[i * 24 + l];
        gPPC[idx] = s;
    }
    for (int idx = tid; idx < 1024; idx += blockDim.x) {
        int i4 = idx >> 7, j = (idx >> 2) & 31, d = idx & 3;
        int src = j * 32 + i4 * 4 + d;
        gWQKV4[idx]        = q_w[src];
        gWQKV4[1024 + idx] = k_w[src];
        gWQKV4[2048 + idx] = v_w[src];
        gWM4[idx]          = m_w[src];
    }
    for (int idx = tid; idx < 9216; idx += blockDim.x) {
        int kt = idx >> 10, i4 = (idx >> 7) & 7, o = (idx >> 2) & 31, d = idx & 3;
        gCWT2[idx] = conv_w[(o * 32 + i4 * 4 + d) * 9 + kt];
    }
}

// ---------------------------------------------------------------------------
// shared memory layout (floats), total 18904 = 75.6 KB -> 3 CTAs/SM
// ---------------------------------------------------------------------------
#define S_XATT  0                 // [216][36]
#define S_W     7776
#define S_XB0   (S_W)             // [24][36]
#define S_XB1   (S_W + 864)
#define S_Q3    (S_W + 1728)      // [24][36]
#define S_K3    (S_W + 2592)
#define S_V3    (S_W + 3456)
#define S_SMX   (S_W + 4320)      // [8][676] (atten2 only now)
// stats overlay (inside SMX region; done before any smx use)
#define S_PSUM  (S_SMX)           // [32][8]
#define S_PSQ   (S_SMX + 256)
#define S_AA    (S_SMX + 512)     // [32][33]
// conv overlay (inside W after attention)
#define S_PPC   (S_W)             // [32][25]
#define S_P1    (S_W + 800)
#define S_P2    (S_W + 1600)
// fixed tail
#define S_BQ    17504
#define S_BK    17536
#define S_BV    17568
#define S_BM    17600
#define S_BMX   17632             // 376 pad 384
#define S_SDL   18016
#define S_VC1   18048
#define S_VC2   18080
#define S_VC3   18112
#define S_PBF   18144
#define S_PWT   18176             // [24][25]
#define S_SWL   18776             // 64
#define S_SWC   18840             // 64
#define S_TOTAL 18904

__global__ __launch_bounds__(NTHR, 3)
void prb_kernel(const float* __restrict__ x,
                const float* __restrict__ ln_g,  const float* __restrict__ ln_b,
                const float* __restrict__ rp_w1, const float* __restrict__ rp_b1,
                const float* __restrict__ rp_w2, const float* __restrict__ rp_b2,
                const float* __restrict__ mask_w, const float* __restrict__ mask_b,
                const float* __restrict__ val_w1, const float* __restrict__ val_b1,
                const float* __restrict__ val_w2, const float* __restrict__ val_b2,
                const float* __restrict__ fuse_gate,
                const float* __restrict__ q_b, const float* __restrict__ k_b,
                const float* __restrict__ v_b, const float* __restrict__ m_b,
                const float* __restrict__ W_logit, const float* __restrict__ W_ctx,
                const float* __restrict__ p_w,   const float* __restrict__ p_b,
                float* __restrict__ out)
{
    extern __shared__ float sm[];
    const int tid = threadIdx.x;
    const size_t base = (size_t)blockIdx.x * 6912;

    float* xatt = sm + S_XATT;
    float* q3   = sm + S_Q3;
    float* k3   = sm + S_K3;
    float* v3   = sm + S_V3;
    float* smx  = sm + S_SMX;
    float* bq   = sm + S_BQ;
    float* bk   = sm + S_BK;
    float* bv   = sm + S_BV;
    float* bm   = sm + S_BM;
    float* sWL  = sm + S_SWL;
    float* sWC  = sm + S_SWC;
    float* bmx  = sm + S_BMX;
    float* sdl  = sm + S_SDL;
    float* vc1  = sm + S_VC1;
    float* vc2  = sm + S_VC2;
    float* vc3  = sm + S_VC3;
    float* pbf  = sm + S_PBF;
    float* pwT  = sm + S_PWT;
    float* aA   = sm + S_AA;
    float* psum = sm + S_PSUM;
    float* psq  = sm + S_PSQ;
    float* ppc  = sm + S_PPC;
    float* p1   = sm + S_P1;
    float* p2   = sm + S_P2;

    const int j32 = tid & 31;
    const int g8  = tid >> 5;

    // ---------------- Phase 1: stage small tables + stats partials --------
    for (int idx = tid; idx < 1024; idx += NTHR) {
        int j = idx >> 5, i = idx & 31;
        aA[j * 33 + i] = gA32[idx];
    }
    for (int idx = tid; idx < 576; idx += NTHR) {
        int lo = idx / 24, l = idx % 24;
        pwT[l * 25 + lo] = p_w[idx];
    }
    for (int idx = tid; idx < 376; idx += NTHR) bmx[idx] = gBmixr[idx];
    if (tid < 64) { sWL[tid] = W_logit[tid]; sWC[tid] = W_ctx[tid]; }
    if (tid < 32) {
        bq[tid] = q_b[tid]; bk[tid] = k_b[tid];
        bv[tid] = v_b[tid]; bm[tid] = m_b[tid];
    }
    if (tid < 24) pbf[tid] = p_b[tid];
    if (tid < 192) {
        int c = tid & 31, g = tid >> 5;
        float4 v = *(const float4*)(x + base + c * 216 + g * 4);
        float* xb = sm + S_XB0;
        int row = g * 4;
        xb[(row + 0) * 36 + c] = v.x;
        xb[(row + 1) * 36 + c] = v.y;
        xb[(row + 2) * 36 + c] = v.z;
        xb[(row + 3) * 36 + c] = v.w;
    }
    {
        int c = tid >> 3, part = tid & 7;
        const float* xp = x + base + c * 216 + part * 27;
        float s = 0.f, sq = 0.f;
#pragma unroll 9
        for (int k2 = 0; k2 < 27; ++k2) {
            float v = xp[k2];
            s += v; sq += v * v;
        }
        psum[c * 8 + part] = s;
        psq [c * 8 + part] = sq;
    }
    __syncthreads();

    // ---------------- Phase 2b: warp-0 scalar chain ----------------
    if (tid < 32) {
        const int c = tid;
        float s = 0.f, sq = 0.f;
#pragma unroll
        for (int p = 0; p < 8; ++p) { s += psum[c * 8 + p]; sq += psq[c * 8 + p]; }
        float pooled = s * (1.f / 216.f);
        float varu = (sq - s * s * (1.f / 216.f)) * (1.f / 215.f);
        float scalec = fmaxf(sqrtf(fmaxf(varu, 0.f)), 1e-3f);

        float mu = pooled;
#pragma unroll
        for (int o = 16; o > 0; o >>= 1) mu += __shfl_xor_sync(0xffffffffu, mu, o);
        mu *= (1.f / 32.f);
        float d = pooled - mu;
        float var = d * d;
#pragma unroll
        for (int o = 16; o > 0; o >>= 1) var += __shfl_xor_sync(0xffffffffu, var, o);
        var *= (1.f / 32.f);
        float pn = d * rsqrtf(var + 1e-5f) * ln_g[c] + ln_b[c];
        vc1[c] = pn; __syncwarp();

        float acc = rp_b1[c];
#pragma unroll
        for (int i = 0; i < 32; ++i) acc += vc1[i] * rp_w1[c * 32 + i];
        vc2[c] = geluf(acc); __syncwarp();

        acc = rp_b2[c];
#pragma unroll
        for (int i = 0; i < 32; ++i) acc += vc2[i] * rp_w2[c * 32 + i];
        vc1[c] = acc; __syncwarp();       // pooled_rule

        acc = mask_b[c];
#pragma unroll
        for (int i = 0; i < 32; ++i) acc += vc1[i] * mask_w[c * 32 + i];
        float M = sigmoidf_(acc);

        acc = val_b1[c];
#pragma unroll
        for (int i = 0; i < 32; ++i) acc += vc1[i] * val_w1[c * 32 + i];
        vc2[c] = geluf(acc); __syncwarp();

        acc = val_b2[c];
#pragma unroll
        for (int i = 0; i < 32; ++i) acc += vc2[i] * val_w2[c * 32 + i];
        float v32 = tanhf(acc) * scalec + pooled;
        float xdo = (1.f - M) * pooled + M * v32;

        float y = xdo;
#pragma unroll
        for (int it = 0; it < 3; ++it) {
            vc3[c] = y; __syncwarp();
            float a2 = xdo;
#pragma unroll
            for (int j = 0; j < 32; ++j) a2 += vc3[j] * aA[c * 33 + j];
            y = a2;
            __syncwarp();
        }
        sdl[c] = sigmoidf_(fuse_gate[0]) * (y - pooled);
    }
    __syncthreads();

    // ---------------- Phase 4: attention per context t ----------------
    for (int t = 0; t < 9; ++t) {
        float* xb = sm + ((t & 1) ? S_XB1 : S_XB0);
        float* xn = sm + ((t & 1) ? S_XB0 : S_XB1);

        // 4a: qkv projection + fuse add + cosine norm (shfl)
        {
            float aq[3], ak[3], av[3];
#pragma unroll
            for (int r = 0; r < 3; ++r) { aq[r] = bq[j32]; ak[r] = bk[j32]; av[r] = bv[j32]; }
#pragma unroll
            for (int i4 = 0; i4 < 8; ++i4) {
                float4 sd4 = *(const float4*)&sdl[i4 * 4];
                float4 wq4 = *(const float4*)&gWQKV4[(i4 * 32 + j32) * 4];
                float4 wk4 = *(const float4*)&gWQKV4[1024 + (i4 * 32 + j32) * 4];
                float4 wv4 = *(const float4*)&gWQKV4[2048 + (i4 * 32 + j32) * 4];
#pragma unroll
                for (int r = 0; r < 3; ++r) {
                    float4 f4 = *(const float4*)&xb[(g8 * 3 + r) * 36 + i4 * 4];
                    float f0 = f4.x + sd4.x, f1 = f4.y + sd4.y;
                    float f2 = f4.z + sd4.z, f3 = f4.w + sd4.w;
                    aq[r] = fmaf(f0, wq4.x, aq[r]); aq[r] = fmaf(f1, wq4.y, aq[r]);
                    aq[r] = fmaf(f2, wq4.z, aq[r]); aq[r] = fmaf(f3, wq4.w, aq[r]);
                    ak[r] = fmaf(f0, wk4.x, ak[r]); ak[r] = fmaf(f1, wk4.y, ak[r]);
                    ak[r] = fmaf(f2, wk4.z, ak[r]); ak[r] = fmaf(f3, wk4.w, ak[r]);
                    av[r] = fmaf(f0, wv4.x, av[r]); av[r] = fmaf(f1, wv4.y, av[r]);
                    av[r] = fmaf(f2, wv4.z, av[r]); av[r] = fmaf(f3, wv4.w, av[r]);
                }
            }
#pragma unroll
            for (int r = 0; r < 3; ++r) {
                float n2 = aq[r] * aq[r];
                n2 += __shfl_xor_sync(0xffffffffu, n2, 1);
                n2 += __shfl_xor_sync(0xffffffffu, n2, 2);
                aq[r] *= 0.5f / fmaxf(sqrtf(n2), 1e-12f);   // 1/sqrt(HD)=0.5 folded
                n2 = ak[r] * ak[r];
                n2 += __shfl_xor_sync(0xffffffffu, n2, 1);
                n2 += __shfl_xor_sync(0xffffffffu, n2, 2);
                ak[r] *= 1.f / fmaxf(sqrtf(n2), 1e-12f);
                n2 = av[r] * av[r];
                n2 += __shfl_xor_sync(0xffffffffu, n2, 1);
                n2 += __shfl_xor_sync(0xffffffffu, n2, 2);
                av[r] *= 1.f / fmaxf(sqrtf(n2), 1e-12f);
                q3[(g8 * 3 + r) * 36 + j32] = aq[r];
                k3[(g8 * 3 + r) * 36 + j32] = ak[r];
                v3[(g8 * 3 + r) * 36 + j32] = av[r];
            }
        }
        __syncthreads();

        // 4cde merged (warps 0-5): logits -> W_logit mix + bias -> shfl softmax
        // -> W_ctx mix, all in registers; only atten2 written to smx.
        // warps 6-7: prefetch next t's x rows.
        if (tid < 192) {
            const int i = tid >> 3, jg = tid & 7;
            float raw[3][8];
#pragma unroll
            for (int h = 0; h < 8; ++h) {
                float4 qh = *(const float4*)&q3[i * 36 + h * 4];
#pragma unroll
                for (int r = 0; r < 3; ++r) {
                    float4 kv = *(const float4*)&k3[(jg * 3 + r) * 36 + h * 4];
                    raw[r][h] = qh.x*kv.x + qh.y*kv.y + qh.z*kv.z + qh.w*kv.w;
                }
            }
            float ml[8][3];
#pragma unroll
            for (int Ho = 0; Ho < 8; ++Ho) {
                float wl[8];
#pragma unroll
                for (int h = 0; h < 8; ++h) wl[h] = sWL[h * 8 + Ho];
#pragma unroll
                for (int r = 0; r < 3; ++r) {
                    float acc = bmx[Ho * 47 + i - (jg * 3 + r) + 23];
#pragma unroll
                    for (int h = 0; h < 8; ++h) acc = fmaf(raw[r][h], wl[h], acc);
                    ml[Ho][r] = acc;
                }
            }
            // softmax per Ho over the 24 j (3 local x 8 jg-lanes)
#pragma unroll
            for (int Ho = 0; Ho < 8; ++Ho) {
                float m = fmaxf(ml[Ho][0], fmaxf(ml[Ho][1], ml[Ho][2]));
                m = fmaxf(m, __shfl_xor_sync(0xffffffffu, m, 1));
                m = fmaxf(m, __shfl_xor_sync(0xffffffffu, m, 2));
                m = fmaxf(m, __shfl_xor_sync(0xffffffffu, m, 4));
                float s0 = __expf(ml[Ho][0] - m);
                float s1 = __expf(ml[Ho][1] - m);
                float s2 = __expf(ml[Ho][2] - m);
                float ssum = s0 + s1 + s2;
                ssum += __shfl_xor_sync(0xffffffffu, ssum, 1);
                ssum += __shfl_xor_sync(0xffffffffu, ssum, 2);
                ssum += __shfl_xor_sync(0xffffffffu, ssum, 4);
                float inv = 1.f / ssum;
                ml[Ho][0] = s0 * inv; ml[Ho][1] = s1 * inv; ml[Ho][2] = s2 * inv;
            }
            // W_ctx mix -> atten2 to smx
#pragma unroll
            for (int Ho = 0; Ho < 8; ++Ho) {
                float wc[8];
#pragma unroll
                for (int h = 0; h < 8; ++h) wc[h] = sWC[h * 8 + Ho];
#pragma unroll
                for (int r = 0; r < 3; ++r) {
                    float acc = 0.f;
#pragma unroll
                    for (int h = 0; h < 8; ++h) acc = fmaf(ml[h][r], wc[h], acc);
                    smx[Ho * 676 + i * 28 + jg * 3 + r] = acc;
                }
            }
        } else if (t < 8) {
            int lt = tid - 192;
#pragma unroll
            for (int k = 0; k < 3; ++k) {
                int idx4 = lt + k * 64;
                int c = idx4 & 31, g = idx4 >> 5;
                float4 v = *(const float4*)(x + base + c * 216 + (t + 1) * 24 + g * 4);
                int row = g * 4;
                xn[(row + 0) * 36 + c] = v.x;
                xn[(row + 1) * 36 + c] = v.y;
                xn[(row + 2) * 36 + c] = v.z;
                xn[(row + 3) * 36 + c] = v.w;
            }
        }
        __syncthreads();

        // 4f: AV -> att into q3 (3 rows per thread-group)
        {
            const int h = j32 >> 2;
            float acc[3] = {0.f, 0.f, 0.f};
#pragma unroll
            for (int j4 = 0; j4 < 6; ++j4) {
                float s4[3][4];
#pragma unroll
                for (int r = 0; r < 3; ++r) {
                    float4 tv = *(const float4*)&smx[h * 676 + (g8 * 3 + r) * 28 + j4 * 4];
                    s4[r][0] = tv.x; s4[r][1] = tv.y; s4[r][2] = tv.z; s4[r][3] = tv.w;
                }
#pragma unroll
                for (int s = 0; s < 4; ++s) {
                    float vv = v3[(j4 * 4 + s) * 36 + j32];
#pragma unroll
                    for (int r = 0; r < 3; ++r)
                        acc[r] = fmaf(s4[r][s], vv, acc[r]);
                }
            }
#pragma unroll
            for (int r = 0; r < 3; ++r)
                q3[(g8 * 3 + r) * 36 + j32] = acc[r];
        }
        __syncthreads();

        // 4g: output projection -> xatt rows of this t
        {
            float am[3];
#pragma unroll
            for (int r = 0; r < 3; ++r) am[r] = bm[j32];
#pragma unroll
            for (int i4 = 0; i4 < 8; ++i4) {
                float4 wm_ = *(const float4*)&gWM4[(i4 * 32 + j32) * 4];
#pragma unroll
                for (int r = 0; r < 3; ++r) {
                    float4 a4 = *(const float4*)&q3[(g8 * 3 + r) * 36 + i4 * 4];
                    am[r] = fmaf(a4.x, wm_.x, am[r]); am[r] = fmaf(a4.y, wm_.y, am[r]);
                    am[r] = fmaf(a4.z, wm_.z, am[r]); am[r] = fmaf(a4.w, wm_.w, am[r]);
                }
            }
#pragma unroll
            for (int r = 0; r < 3; ++r)
                xatt[(t * 24 + g8 * 3 + r) * 36 + j32] = am[r];
        }
        __syncthreads();
    }

    // ---------------- Phase 5: conv over contexts (all 256 threads) --------
    for (int idx = tid; idx < 768; idx += NTHR) {
        int o = idx / 24, l = idx % 24;
        ppc[o * 25 + l] = gPPC[idx];
    }
    __syncthreads();
    {
        const int lbase = g8 * 3;
        float acc[3];
#pragma unroll
        for (int r = 0; r < 3; ++r) acc[r] = ppc[j32 * 25 + lbase + r];
#pragma unroll
        for (int kt = 0; kt < 8; ++kt) {
#pragma unroll
            for (int i4 = 0; i4 < 8; ++i4) {
                float4 w4 = *(const float4*)&gCWT2[((kt * 8 + i4) * 32 + j32) * 4];
#pragma unroll
                for (int r = 0; r < 3; ++r) {
                    float4 f4 = *(const float4*)&xatt[(kt * 24 + lbase + r) * 36 + i4 * 4];
                    acc[r] = fmaf(f4.x, w4.x, acc[r]);
                    acc[r] = fmaf(f4.y, w4.y, acc[r]);
                    acc[r] = fmaf(f4.z, w4.z, acc[r]);
                    acc[r] = fmaf(f4.w, w4.w, acc[r]);
                }
            }
        }
#pragma unroll
        for (int r = 0; r < 3; ++r)
            p1[j32 * 25 + lbase + r] = fmaxf(acc[r], 0.f);
    }
    __syncthreads();

    // ---------------- Phase 6: token linear ----------------
    for (int idx = tid; idx < 768; idx += NTHR) {
        int o = idx / 24, lo = idx % 24;
        float acc = pbf[lo];
#pragma unroll
        for (int l = 0; l < 24; ++l)
            acc = fmaf(p1[o * 25 + l], pwT[l * 25 + lo], acc);
        p2[o * 25 + lo] = acc;
    }
    __syncthreads();

    // ---------------- Phase 7: output (conflict-free remap) ----------------
    for (int idx4 = tid; idx4 < 1728; idx4 += NTHR) {
        int c = idx4 & 31, g = idx4 >> 5;
        int tl = g * 4;
        float4 v;
        v.x = xatt[(tl + 0) * 36 + c];
        v.y = xatt[(tl + 1) * 36 + c];
        v.z = xatt[(tl + 2) * 36 + c];
        v.w = xatt[(tl + 3) * 36 + c];
        if (g >= 48) {
            v.x -= p2[c * 25 + (tl - 192)];
            v.y -= p2[c * 25 + (tl - 191)];
            v.z -= p2[c * 25 + (tl - 190)];
            v.w -= p2[c * 25 + (tl - 189)];
        }
        *(float4*)(out + base + c * 216 + tl) = v;
    }
}

extern "C" void kernel_launch(void* const* d_in, const int* in_sizes, int n_in,
                              void* d_out, int out_size) {
    const float* x        = (const float*)d_in[0];
    const float* ln_g     = (const float*)d_in[1];
    const float* ln_b     = (const float*)d_in[2];
    const float* rp_w1    = (const float*)d_in[3];
    const float* rp_b1    = (const float*)d_in[4];
    const float* rp_w2    = (const float*)d_in[5];
    const float* rp_b2    = (const float*)d_in[6];
    const float* W_causal = (const float*)d_in[7];
    const float* mask_w   = (const float*)d_in[8];
    const float* mask_b   = (const float*)d_in[9];
    const float* val_w1   = (const float*)d_in[10];
    const float* val_b1   = (const float*)d_in[11];
    const float* val_w2   = (const float*)d_in[12];
    const float* val_b2   = (const float*)d_in[13];
    const float* fuse_g   = (const float*)d_in[14];
    const float* q_w      = (const float*)d_in[15];
    const float* q_b      = (const float*)d_in[16];
    const float* k_w      = (const float*)d_in[17];
    const float* k_b      = (const float*)d_in[18];
    const float* v_w      = (const float*)d_in[19];
    const float* v_b      = (const float*)d_in[20];
    const float* m_w      = (const float*)d_in[21];
    const float* m_b      = (const float*)d_in[22];
    const float* W_logit  = (const float*)d_in[23];
    const float* W_ctx    = (const float*)d_in[24];
    const float* rpb      = (const float*)d_in[25];
    const float* pre_p    = (const float*)d_in[26];
    const float* conv_w   = (const float*)d_in[27];
    const float* conv_b   = (const float*)d_in[28];
    const float* p_w      = (const float*)d_in[29];
    const float* p_b      = (const float*)d_in[30];
    float* out = (float*)d_out;

    const int smem_bytes = S_TOTAL * 4;
    cudaFuncSetAttribute(prb_kernel, cudaFuncAttributeMaxDynamicSharedMemorySize,
                         smem_bytes);

    prb_precompute<<<1, 256>>>(W_causal, W_logit, rpb, conv_w, conv_b, pre_p,
                               q_w, k_w, v_w, m_w);

    int B = in_sizes[0] / 6912;
    prb_kernel<<<B, NTHR, smem_bytes>>>(
        x, ln_g, ln_b, rp_w1, rp_b1, rp_w2, rp_b2,
        mask_w, mask_b, val_w1, val_b1, val_w2, val_b2, fuse_g,
        q_b, k_b, v_b, m_b, W_logit, W_ctx, p_w, p_b, out);
}

// round 16
// speedup vs baseline: 1.2477x; 1.0707x over previous
#include <cuda_runtime.h>
#include <cuda_bf16.h>
#include <math.h>

// ============================================================================
// PredictiveReasoningBlock fused monolith, one CTA per batch element.
// Round 15: R14 + head-mix weights in __constant__ (off the LSU pipe),
// hoisted bias scalars. 3 CTAs/SM, streamed x, merged logits/softmax/mix.
// Shapes: B=4096, D=32, T=9, L=24, H=8, HD=4.
// ============================================================================

#define NTHR 256

__device__ float gA32[1024];     // 0.9*softplus(W_causal)*(1-I), row-normalized
__device__ float gBmixr[376];    // sum_h W_logit[h,Ho]*rel_pos_bias[h,r] (8x47)
__device__ float gPPC[768];      // conv_b[o] + sum_i conv_w[o,i,8]*pre_prompt[i,l]
__device__ float gWQKV4[3072];   // [m][i4][lane][4]: W_m[lane][i4*4+d]
__device__ float gWM4[1024];     // [i4][lane][4]
__device__ float gCWT2[9216];    // [kt][i4][o][4] = conv_w[o][i4*4+d][kt]

__constant__ float cWL[64];
__constant__ float cWC[64];

__device__ __forceinline__ float geluf(float x) {
    return 0.5f * x * (1.0f + erff(x * 0.7071067811865476f));
}
__device__ __forceinline__ float sigmoidf_(float x) {
    return 1.0f / (1.0f + __expf(-x));
}

__global__ void prb_precompute(const float* __restrict__ Wc,
                               const float* __restrict__ WL,
                               const float* __restrict__ rpb,
                               const float* __restrict__ conv_w,
                               const float* __restrict__ conv_b,
                               const float* __restrict__ pre_prompt,
                               const float* __restrict__ q_w,
                               const float* __restrict__ k_w,
                               const float* __restrict__ v_w,
                               const float* __restrict__ m_w) {
    int tid = threadIdx.x;
    if (tid < 32) {
        float a[32];
        float rs = 0.f;
#pragma unroll
        for (int j = 0; j < 32; ++j) {
            float w = Wc[tid * 32 + j];
            float sp = (w > 20.f) ? w : log1pf(expf(w));
            if (j == tid) sp = 0.f;
            a[j] = sp;
            rs += sp;
        }
        float inv = 0.9f / (rs + 1e-6f);
#pragma unroll
        for (int j = 0; j < 32; ++j) gA32[tid * 32 + j] = a[j] * inv;
    }
    for (int idx = tid; idx < 376; idx += blockDim.x) {
        int Ho = idx / 47, r = idx % 47;
        float s = 0.f;
#pragma unroll
        for (int h = 0; h < 8; ++h) s += WL[h * 8 + Ho] * rpb[h * 47 + r];
        gBmixr[idx] = s;
    }
    for (int idx = tid; idx < 768; idx += blockDim.x) {
        int o = idx / 24, l = idx % 24;
        float s = conv_b[o];
#pragma unroll
        for (int i = 0; i < 32; ++i)
            s += conv_w[(o * 32 + i) * 9 + 8] * pre_prompt[i * 24 + l];
        gPPC[idx] = s;
    }
    for (int idx = tid; idx < 1024; idx += blockDim.x) {
        int i4 = idx >> 7, j = (idx >> 2) & 31, d = idx & 3;
        int src = j * 32 + i4 * 4 + d;
        gWQKV4[idx]        = q_w[src];
        gWQKV4[1024 + idx] = k_w[src];
        gWQKV4[2048 + idx] = v_w[src];
        gWM4[idx]          = m_w[src];
    }
    for (int idx = tid; idx < 9216; idx += blockDim.x) {
        int kt = idx >> 10, i4 = (idx >> 7) & 7, o = (idx >> 2) & 31, d = idx & 3;
        gCWT2[idx] = conv_w[(o * 32 + i4 * 4 + d) * 9 + kt];
    }
}

// ---------------------------------------------------------------------------
// shared memory layout (floats), total 18648 = 74.6 KB -> 3 CTAs/SM
// ---------------------------------------------------------------------------
#define S_XATT  0                 // [216][36]
#define S_W     7776
#define S_XB0   (S_W)             // [24][36]
#define S_XB1   (S_W + 864)
#define S_Q3    (S_W + 1728)      // [24][36]
#define S_K3    (S_W + 2592)
#define S_V3    (S_W + 3456)
#define S_SMX   (S_W + 4320)      // [8][676] (atten2)
// stats overlay (inside SMX region; done before any smx use)
#define S_PSUM  (S_SMX)           // [32][8]
#define S_PSQ   (S_SMX + 256)
#define S_AA    (S_SMX + 512)     // [32][33]
// conv overlay (inside W after attention)
#define S_PPC   (S_W)             // [32][25]
#define S_P1    (S_W + 800)
#define S_P2    (S_W + 1600)
// fixed tail (starts at 7776+4320+5408 = 17504)
#define S_BMX   17504             // 376 pad 384
#define S_SDL   17888
#define S_VC1   17920
#define S_VC2   17952
#define S_VC3   17984
#define S_PBF   18016
#define S_PWT   18048             // [24][25] = 600
#define S_TOTAL 18648

__global__ __launch_bounds__(NTHR, 3)
void prb_kernel(const float* __restrict__ x,
                const float* __restrict__ ln_g,  const float* __restrict__ ln_b,
                const float* __restrict__ rp_w1, const float* __restrict__ rp_b1,
                const float* __restrict__ rp_w2, const float* __restrict__ rp_b2,
                const float* __restrict__ mask_w, const float* __restrict__ mask_b,
                const float* __restrict__ val_w1, const float* __restrict__ val_b1,
                const float* __restrict__ val_w2, const float* __restrict__ val_b2,
                const float* __restrict__ fuse_gate,
                const float* __restrict__ q_b, const float* __restrict__ k_b,
                const float* __restrict__ v_b, const float* __restrict__ m_b,
                const float* __restrict__ p_w,   const float* __restrict__ p_b,
                float* __restrict__ out)
{
    extern __shared__ float sm[];
    const int tid = threadIdx.x;
    const size_t base = (size_t)blockIdx.x * 6912;

    float* xatt = sm + S_XATT;
    float* q3   = sm + S_Q3;
    float* k3   = sm + S_K3;
    float* v3   = sm + S_V3;
    float* smx  = sm + S_SMX;
    float* bmx  = sm + S_BMX;
    float* sdl  = sm + S_SDL;
    float* vc1  = sm + S_VC1;
    float* vc2  = sm + S_VC2;
    float* vc3  = sm + S_VC3;
    float* pbf  = sm + S_PBF;
    float* pwT  = sm + S_PWT;
    float* aA   = sm + S_AA;
    float* psum = sm + S_PSUM;
    float* psq  = sm + S_PSQ;
    float* ppc  = sm + S_PPC;
    float* p1   = sm + S_P1;
    float* p2   = sm + S_P2;

    const int j32 = tid & 31;
    const int g8  = tid >> 5;

    // per-thread bias scalars (constant across the t loop)
    const float bq_ = q_b[j32];
    const float bk_ = k_b[j32];
    const float bv_ = v_b[j32];
    const float bm_ = m_b[j32];

    // ---------------- Phase 1: stage small tables + stats partials --------
    for (int idx = tid; idx < 1024; idx += NTHR) {
        int j = idx >> 5, i = idx & 31;
        aA[j * 33 + i] = gA32[idx];
    }
    for (int idx = tid; idx < 576; idx += NTHR) {
        int lo = idx / 24, l = idx % 24;
        pwT[l * 25 + lo] = p_w[idx];
    }
    for (int idx = tid; idx < 376; idx += NTHR) bmx[idx] = gBmixr[idx];
    if (tid < 24) pbf[tid] = p_b[tid];
    if (tid < 192) {
        int c = tid & 31, g = tid >> 5;
        float4 v = *(const float4*)(x + base + c * 216 + g * 4);
        float* xb = sm + S_XB0;
        int row = g * 4;
        xb[(row + 0) * 36 + c] = v.x;
        xb[(row + 1) * 36 + c] = v.y;
        xb[(row + 2) * 36 + c] = v.z;
        xb[(row + 3) * 36 + c] = v.w;
    }
    {
        int c = tid >> 3, part = tid & 7;
        const float* xp = x + base + c * 216 + part * 27;
        float s = 0.f, sq = 0.f;
#pragma unroll 9
        for (int k2 = 0; k2 < 27; ++k2) {
            float v = xp[k2];
            s += v; sq += v * v;
        }
        psum[c * 8 + part] = s;
        psq [c * 8 + part] = sq;
    }
    __syncthreads();

    // ---------------- Phase 2b: warp-0 scalar chain ----------------
    if (tid < 32) {
        const int c = tid;
        float s = 0.f, sq = 0.f;
#pragma unroll
        for (int p = 0; p < 8; ++p) { s += psum[c * 8 + p]; sq += psq[c * 8 + p]; }
        float pooled = s * (1.f / 216.f);
        float varu = (sq - s * s * (1.f / 216.f)) * (1.f / 215.f);
        float scalec = fmaxf(sqrtf(fmaxf(varu, 0.f)), 1e-3f);

        float mu = pooled;
#pragma unroll
        for (int o = 16; o > 0; o >>= 1) mu += __shfl_xor_sync(0xffffffffu, mu, o);
        mu *= (1.f / 32.f);
        float d = pooled - mu;
        float var = d * d;
#pragma unroll
        for (int o = 16; o > 0; o >>= 1) var += __shfl_xor_sync(0xffffffffu, var, o);
        var *= (1.f / 32.f);
        float pn = d * rsqrtf(var + 1e-5f) * ln_g[c] + ln_b[c];
        vc1[c] = pn; __syncwarp();

        float acc = rp_b1[c];
#pragma unroll
        for (int i = 0; i < 32; ++i) acc += vc1[i] * rp_w1[c * 32 + i];
        vc2[c] = geluf(acc); __syncwarp();

        acc = rp_b2[c];
#pragma unroll
        for (int i = 0; i < 32; ++i) acc += vc2[i] * rp_w2[c * 32 + i];
        vc1[c] = acc; __syncwarp();       // pooled_rule

        acc = mask_b[c];
#pragma unroll
        for (int i = 0; i < 32; ++i) acc += vc1[i] * mask_w[c * 32 + i];
        float M = sigmoidf_(acc);

        acc = val_b1[c];
#pragma unroll
        for (int i = 0; i < 32; ++i) acc += vc1[i] * val_w1[c * 32 + i];
        vc2[c] = geluf(acc); __syncwarp();

        acc = val_b2[c];
#pragma unroll
        for (int i = 0; i < 32; ++i) acc += vc2[i] * val_w2[c * 32 + i];
        float v32 = tanhf(acc) * scalec + pooled;
        float xdo = (1.f - M) * pooled + M * v32;

        float y = xdo;
#pragma unroll
        for (int it = 0; it < 3; ++it) {
            vc3[c] = y; __syncwarp();
            float a2 = xdo;
#pragma unroll
            for (int j = 0; j < 32; ++j) a2 += vc3[j] * aA[c * 33 + j];
            y = a2;
            __syncwarp();
        }
        sdl[c] = sigmoidf_(fuse_gate[0]) * (y - pooled);
    }
    __syncthreads();

    // ---------------- Phase 4: attention per context t ----------------
    for (int t = 0; t < 9; ++t) {
        float* xb = sm + ((t & 1) ? S_XB1 : S_XB0);
        float* xn = sm + ((t & 1) ? S_XB0 : S_XB1);

        // 4a: qkv projection + fuse add + cosine norm (shfl)
        {
            float aq[3], ak[3], av[3];
#pragma unroll
            for (int r = 0; r < 3; ++r) { aq[r] = bq_; ak[r] = bk_; av[r] = bv_; }
#pragma unroll
            for (int i4 = 0; i4 < 8; ++i4) {
                float4 sd4 = *(const float4*)&sdl[i4 * 4];
                float4 wq4 = *(const float4*)&gWQKV4[(i4 * 32 + j32) * 4];
                float4 wk4 = *(const float4*)&gWQKV4[1024 + (i4 * 32 + j32) * 4];
                float4 wv4 = *(const float4*)&gWQKV4[2048 + (i4 * 32 + j32) * 4];
#pragma unroll
                for (int r = 0; r < 3; ++r) {
                    float4 f4 = *(const float4*)&xb[(g8 * 3 + r) * 36 + i4 * 4];
                    float f0 = f4.x + sd4.x, f1 = f4.y + sd4.y;
                    float f2 = f4.z + sd4.z, f3 = f4.w + sd4.w;
                    aq[r] = fmaf(f0, wq4.x, aq[r]); aq[r] = fmaf(f1, wq4.y, aq[r]);
                    aq[r] = fmaf(f2, wq4.z, aq[r]); aq[r] = fmaf(f3, wq4.w, aq[r]);
                    ak[r] = fmaf(f0, wk4.x, ak[r]); ak[r] = fmaf(f1, wk4.y, ak[r]);
                    ak[r] = fmaf(f2, wk4.z, ak[r]); ak[r] = fmaf(f3, wk4.w, ak[r]);
                    av[r] = fmaf(f0, wv4.x, av[r]); av[r] = fmaf(f1, wv4.y, av[r]);
                    av[r] = fmaf(f2, wv4.z, av[r]); av[r] = fmaf(f3, wv4.w, av[r]);
                }
            }
#pragma unroll
            for (int r = 0; r < 3; ++r) {
                float n2 = aq[r] * aq[r];
                n2 += __shfl_xor_sync(0xffffffffu, n2, 1);
                n2 += __shfl_xor_sync(0xffffffffu, n2, 2);
                aq[r] *= 0.5f / fmaxf(sqrtf(n2), 1e-12f);   // 1/sqrt(HD)=0.5 folded
                n2 = ak[r] * ak[r];
                n2 += __shfl_xor_sync(0xffffffffu, n2, 1);
                n2 += __shfl_xor_sync(0xffffffffu, n2, 2);
                ak[r] *= 1.f / fmaxf(sqrtf(n2), 1e-12f);
                n2 = av[r] * av[r];
                n2 += __shfl_xor_sync(0xffffffffu, n2, 1);
                n2 += __shfl_xor_sync(0xffffffffu, n2, 2);
                av[r] *= 1.f / fmaxf(sqrtf(n2), 1e-12f);
                q3[(g8 * 3 + r) * 36 + j32] = aq[r];
                k3[(g8 * 3 + r) * 36 + j32] = ak[r];
                v3[(g8 * 3 + r) * 36 + j32] = av[r];
            }
        }
        __syncthreads();

        // 4cde merged (warps 0-5): logits -> W_logit mix + bias -> shfl softmax
        // -> W_ctx mix; W_logit/W_ctx via constant port. warps 6-7: prefetch.
        if (tid < 192) {
            const int i = tid >> 3, jg = tid & 7;
            float raw[3][8];
#pragma unroll
            for (int h = 0; h < 8; ++h) {
                float4 qh = *(const float4*)&q3[i * 36 + h * 4];
#pragma unroll
                for (int r = 0; r < 3; ++r) {
                    float4 kv = *(const float4*)&k3[(jg * 3 + r) * 36 + h * 4];
                    raw[r][h] = qh.x*kv.x + qh.y*kv.y + qh.z*kv.z + qh.w*kv.w;
                }
            }
            float ml[8][3];
#pragma unroll
            for (int Ho = 0; Ho < 8; ++Ho) {
#pragma unroll
                for (int r = 0; r < 3; ++r) {
                    float acc = bmx[Ho * 47 + i - (jg * 3 + r) + 23];
#pragma unroll
                    for (int h = 0; h < 8; ++h)
                        acc = fmaf(raw[r][h], cWL[h * 8 + Ho], acc);
                    ml[Ho][r] = acc;
                }
            }
#pragma unroll
            for (int Ho = 0; Ho < 8; ++Ho) {
                float m = fmaxf(ml[Ho][0], fmaxf(ml[Ho][1], ml[Ho][2]));
                m = fmaxf(m, __shfl_xor_sync(0xffffffffu, m, 1));
                m = fmaxf(m, __shfl_xor_sync(0xffffffffu, m, 2));
                m = fmaxf(m, __shfl_xor_sync(0xffffffffu, m, 4));
                float s0 = __expf(ml[Ho][0] - m);
                float s1 = __expf(ml[Ho][1] - m);
                float s2 = __expf(ml[Ho][2] - m);
                float ssum = s0 + s1 + s2;
                ssum += __shfl_xor_sync(0xffffffffu, ssum, 1);
                ssum += __shfl_xor_sync(0xffffffffu, ssum, 2);
                ssum += __shfl_xor_sync(0xffffffffu, ssum, 4);
                float inv = 1.f / ssum;
                ml[Ho][0] = s0 * inv; ml[Ho][1] = s1 * inv; ml[Ho][2] = s2 * inv;
            }
#pragma unroll
            for (int Ho = 0; Ho < 8; ++Ho) {
#pragma unroll
                for (int r = 0; r < 3; ++r) {
                    float acc = 0.f;
#pragma unroll
                    for (int h = 0; h < 8; ++h)
                        acc = fmaf(ml[h][r], cWC[h * 8 + Ho], acc);
                    smx[Ho * 676 + i * 28 + jg * 3 + r] = acc;
                }
            }
        } else if (t < 8) {
            int lt = tid - 192;
#pragma unroll
            for (int k = 0; k < 3; ++k) {
                int idx4 = lt + k * 64;
                int c = idx4 & 31, g = idx4 >> 5;
                float4 v = *(const float4*)(x + base + c * 216 + (t + 1) * 24 + g * 4);
                int row = g * 4;
                xn[(row + 0) * 36 + c] = v.x;
                xn[(row + 1) * 36 + c] = v.y;
                xn[(row + 2) * 36 + c] = v.z;
                xn[(row + 3) * 36 + c] = v.w;
            }
        }
        __syncthreads();

        // 4f: AV -> att into q3 (3 rows per thread-group)
        {
            const int h = j32 >> 2;
            float acc[3] = {0.f, 0.f, 0.f};
#pragma unroll
            for (int j4 = 0; j4 < 6; ++j4) {
                float s4[3][4];
#pragma unroll
                for (int r = 0; r < 3; ++r) {
                    float4 tv = *(const float4*)&smx[h * 676 + (g8 * 3 + r) * 28 + j4 * 4];
                    s4[r][0] = tv.x; s4[r][1] = tv.y; s4[r][2] = tv.z; s4[r][3] = tv.w;
                }
#pragma unroll
                for (int s = 0; s < 4; ++s) {
                    float vv = v3[(j4 * 4 + s) * 36 + j32];
#pragma unroll
                    for (int r = 0; r < 3; ++r)
                        acc[r] = fmaf(s4[r][s], vv, acc[r]);
                }
            }
#pragma unroll
            for (int r = 0; r < 3; ++r)
                q3[(g8 * 3 + r) * 36 + j32] = acc[r];
        }
        __syncthreads();

        // 4g: output projection -> xatt rows of this t
        {
            float am[3];
#pragma unroll
            for (int r = 0; r < 3; ++r) am[r] = bm_;
#pragma unroll
            for (int i4 = 0; i4 < 8; ++i4) {
                float4 wm_ = *(const float4*)&gWM4[(i4 * 32 + j32) * 4];
#pragma unroll
                for (int r = 0; r < 3; ++r) {
                    float4 a4 = *(const float4*)&q3[(g8 * 3 + r) * 36 + i4 * 4];
                    am[r] = fmaf(a4.x, wm_.x, am[r]); am[r] = fmaf(a4.y, wm_.y, am[r]);
                    am[r] = fmaf(a4.z, wm_.z, am[r]); am[r] = fmaf(a4.w, wm_.w, am[r]);
                }
            }
#pragma unroll
            for (int r = 0; r < 3; ++r)
                xatt[(t * 24 + g8 * 3 + r) * 36 + j32] = am[r];
        }
        __syncthreads();
    }

    // ---------------- Phase 5: conv over contexts (all 256 threads) --------
    for (int idx = tid; idx < 768; idx += NTHR) {
        int o = idx / 24, l = idx % 24;
        ppc[o * 25 + l] = gPPC[idx];
    }
    __syncthreads();
    {
        const int lbase = g8 * 3;
        float acc[3];
#pragma unroll
        for (int r = 0; r < 3; ++r) acc[r] = ppc[j32 * 25 + lbase + r];
#pragma unroll
        for (int kt = 0; kt < 8; ++kt) {
#pragma unroll
            for (int i4 = 0; i4 < 8; ++i4) {
                float4 w4 = *(const float4*)&gCWT2[((kt * 8 + i4) * 32 + j32) * 4];
#pragma unroll
                for (int r = 0; r < 3; ++r) {
                    float4 f4 = *(const float4*)&xatt[(kt * 24 + lbase + r) * 36 + i4 * 4];
                    acc[r] = fmaf(f4.x, w4.x, acc[r]);
                    acc[r] = fmaf(f4.y, w4.y, acc[r]);
                    acc[r] = fmaf(f4.z, w4.z, acc[r]);
                    acc[r] = fmaf(f4.w, w4.w, acc[r]);
                }
            }
        }
#pragma unroll
        for (int r = 0; r < 3; ++r)
            p1[j32 * 25 + lbase + r] = fmaxf(acc[r], 0.f);
    }
    __syncthreads();

    // ---------------- Phase 6: token linear ----------------
    for (int idx = tid; idx < 768; idx += NTHR) {
        int o = idx / 24, lo = idx % 24;
        float acc = pbf[lo];
#pragma unroll
        for (int l = 0; l < 24; ++l)
            acc = fmaf(p1[o * 25 + l], pwT[l * 25 + lo], acc);
        p2[o * 25 + lo] = acc;
    }
    __syncthreads();

    // ---------------- Phase 7: output (conflict-free remap) ----------------
    for (int idx4 = tid; idx4 < 1728; idx4 += NTHR) {
        int c = idx4 & 31, g = idx4 >> 5;
        int tl = g * 4;
        float4 v;
        v.x = xatt[(tl + 0) * 36 + c];
        v.y = xatt[(tl + 1) * 36 + c];
        v.z = xatt[(tl + 2) * 36 + c];
        v.w = xatt[(tl + 3) * 36 + c];
        if (g >= 48) {
            v.x -= p2[c * 25 + (tl - 192)];
            v.y -= p2[c * 25 + (tl - 191)];
            v.z -= p2[c * 25 + (tl - 190)];
            v.w -= p2[c * 25 + (tl - 189)];
        }
        *(float4*)(out + base + c * 216 + tl) = v;
    }
}

extern "C" void kernel_launch(void* const* d_in, const int* in_sizes, int n_in,
                              void* d_out, int out_size) {
    const float* x        = (const float*)d_in[0];
    const float* ln_g     = (const float*)d_in[1];
    const float* ln_b     = (const float*)d_in[2];
    const float* rp_w1    = (const float*)d_in[3];
    const float* rp_b1    = (const float*)d_in[4];
    const float* rp_w2    = (const float*)d_in[5];
    const float* rp_b2    = (const float*)d_in[6];
    const float* W_causal = (const float*)d_in[7];
    const float* mask_w   = (const float*)d_in[8];
    const float* mask_b   = (const float*)d_in[9];
    const float* val_w1   = (const float*)d_in[10];
    const float* val_b1   = (const float*)d_in[11];
    const float* val_w2   = (const float*)d_in[12];
    const float* val_b2   = (const float*)d_in[13];
    const float* fuse_g   = (const float*)d_in[14];
    const float* q_w      = (const float*)d_in[15];
    const float* q_b      = (const float*)d_in[16];
    const float* k_w      = (const float*)d_in[17];
    const float* k_b      = (const float*)d_in[18];
    const float* v_w      = (const float*)d_in[19];
    const float* v_b      = (const float*)d_in[20];
    const float* m_w      = (const float*)d_in[21];
    const float* m_b      = (const float*)d_in[22];
    const float* W_logit  = (const float*)d_in[23];
    const float* W_ctx    = (const float*)d_in[24];
    const float* rpb      = (const float*)d_in[25];
    const float* pre_p    = (const float*)d_in[26];
    const float* conv_w   = (const float*)d_in[27];
    const float* conv_b   = (const float*)d_in[28];
    const float* p_w      = (const float*)d_in[29];
    const float* p_b      = (const float*)d_in[30];
    float* out = (float*)d_out;

    const int smem_bytes = S_TOTAL * 4;
    cudaFuncSetAttribute(prb_kernel, cudaFuncAttributeMaxDynamicSharedMemorySize,
                         smem_bytes);

    cudaMemcpyToSymbolAsync(cWL, W_logit, 64 * sizeof(float), 0,
                            cudaMemcpyDeviceToDevice);
    cudaMemcpyToSymbolAsync(cWC, W_ctx, 64 * sizeof(float), 0,
                            cudaMemcpyDeviceToDevice);

    prb_precompute<<<1, 256>>>(W_causal, W_logit, rpb, conv_w, conv_b, pre_p,
                               q_w, k_w, v_w, m_w);

    int B = in_sizes[0] / 6912;
    prb_kernel<<<B, NTHR, smem_bytes>>>(
        x, ln_g, ln_b, rp_w1, rp_b1, rp_w2, rp_b2,
        mask_w, mask_b, val_w1, val_b1, val_w2, val_b2, fuse_g,
        q_b, k_b, v_b, m_b, p_w, p_b, out);
}

// round 17
// speedup vs baseline: 1.2935x; 1.0366x over previous
#include <cuda_runtime.h>
#include <cuda_bf16.h>
#include <math.h>

// ============================================================================
// PredictiveReasoningBlock fused monolith, one CTA per batch element.
// Round 16: xatt tile moved to global (gXATT, L2-resident) -> smem 43.5 KB ->
// 4 CTAs/SM; merged logit phase r-serialized to fit the 64-reg cap.
// Shapes: B=4096, D=32, T=9, L=24, H=8, HD=4.
// ============================================================================

#define NTHR 256
#define MAXB 4096

__device__ float gA32[1024];     // 0.9*softplus(W_causal)*(1-I), row-normalized
__device__ float gBmixr[376];    // sum_h W_logit[h,Ho]*rel_pos_bias[h,r] (8x47)
__device__ float gPPC[768];      // conv_b[o] + sum_i conv_w[o,i,8]*pre_prompt[i,l]
__device__ float gWQKV4[3072];   // [m][i4][lane][4]: W_m[lane][i4*4+d]
__device__ float gWM4[1024];     // [i4][lane][4]
__device__ float gCWT2[9216];    // [kt][i4][o][4] = conv_w[o][i4*4+d][kt]
__device__ float gXATT[(size_t)MAXB * 6912];   // x_att [b][tl][c]

__constant__ float cWL[64];
__constant__ float cWC[64];

__device__ __forceinline__ float geluf(float x) {
    return 0.5f * x * (1.0f + erff(x * 0.7071067811865476f));
}
__device__ __forceinline__ float sigmoidf_(float x) {
    return 1.0f / (1.0f + __expf(-x));
}

__global__ void prb_precompute(const float* __restrict__ Wc,
                               const float* __restrict__ WL,
                               const float* __restrict__ rpb,
                               const float* __restrict__ conv_w,
                               const float* __restrict__ conv_b,
                               const float* __restrict__ pre_prompt,
                               const float* __restrict__ q_w,
                               const float* __restrict__ k_w,
                               const float* __restrict__ v_w,
                               const float* __restrict__ m_w) {
    int tid = threadIdx.x;
    if (tid < 32) {
        float a[32];
        float rs = 0.f;
#pragma unroll
        for (int j = 0; j < 32; ++j) {
            float w = Wc[tid * 32 + j];
            float sp = (w > 20.f) ? w : log1pf(expf(w));
            if (j == tid) sp = 0.f;
            a[j] = sp;
            rs += sp;
        }
        float inv = 0.9f / (rs + 1e-6f);
#pragma unroll
        for (int j = 0; j < 32; ++j) gA32[tid * 32 + j] = a[j] * inv;
    }
    for (int idx = tid; idx < 376; idx += blockDim.x) {
        int Ho = idx / 47, r = idx % 47;
        float s = 0.f;
#pragma unroll
        for (int h = 0; h < 8; ++h) s += WL[h * 8 + Ho] * rpb[h * 47 + r];
        gBmixr[idx] = s;
    }
    for (int idx = tid; idx < 768; idx += blockDim.x) {
        int o = idx / 24, l = idx % 24;
        float s = conv_b[o];
#pragma unroll
        for (int i = 0; i < 32; ++i)
            s += conv_w[(o * 32 + i) * 9 + 8] * pre_prompt[i * 24 + l];
        gPPC[idx] = s;
    }
    for (int idx = tid; idx < 1024; idx += blockDim.x) {
        int i4 = idx >> 7, j = (idx >> 2) & 31, d = idx & 3;
        int src = j * 32 + i4 * 4 + d;
        gWQKV4[idx]        = q_w[src];
        gWQKV4[1024 + idx] = k_w[src];
        gWQKV4[2048 + idx] = v_w[src];
        gWM4[idx]          = m_w[src];
    }
    for (int idx = tid; idx < 9216; idx += blockDim.x) {
        int kt = idx >> 10, i4 = (idx >> 7) & 7, o = (idx >> 2) & 31, d = idx & 3;
        gCWT2[idx] = conv_w[(o * 32 + i4 * 4 + d) * 9 + kt];
    }
}

// ---------------------------------------------------------------------------
// shared memory layout (floats), total 10872 = 43.5 KB -> 4 CTAs/SM
// ---------------------------------------------------------------------------
#define S_XB0   0                 // [24][36]
#define S_XB1   864
#define S_Q3    1728              // [24][36]
#define S_K3    2592
#define S_V3    3456
#define S_SMX   4320              // [8][676] = 5408, ends 9728
// stats overlay (inside SMX; used before any smx access)
#define S_PSUM  (S_SMX)           // [32][8]
#define S_PSQ   (S_SMX + 256)
#define S_AA    (S_SMX + 512)     // [32][33]
// conv overlay (over XB/Q3 after attention)
#define S_PPC   0                 // [32][25]
#define S_P1    800
#define S_P2    1600
// fixed tail
#define S_BMX   9728              // 376 pad 384
#define S_SDL   10112
#define S_VC1   10144
#define S_VC2   10176
#define S_VC3   10208
#define S_PBF   10240
#define S_PWT   10272             // [24][25] = 600
#define S_TOTAL 10872

__global__ __launch_bounds__(NTHR, 4)
void prb_kernel(const float* __restrict__ x,
                const float* __restrict__ ln_g,  const float* __restrict__ ln_b,
                const float* __restrict__ rp_w1, const float* __restrict__ rp_b1,
                const float* __restrict__ rp_w2, const float* __restrict__ rp_b2,
                const float* __restrict__ mask_w, const float* __restrict__ mask_b,
                const float* __restrict__ val_w1, const float* __restrict__ val_b1,
                const float* __restrict__ val_w2, const float* __restrict__ val_b2,
                const float* __restrict__ fuse_gate,
                const float* __restrict__ q_b, const float* __restrict__ k_b,
                const float* __restrict__ v_b, const float* __restrict__ m_b,
                const float* __restrict__ p_w,   const float* __restrict__ p_b,
                float* __restrict__ out)
{
    extern __shared__ float sm[];
    const int tid = threadIdx.x;
    const size_t base = (size_t)blockIdx.x * 6912;

    float* q3   = sm + S_Q3;
    float* k3   = sm + S_K3;
    float* v3   = sm + S_V3;
    float* smx  = sm + S_SMX;
    float* bmx  = sm + S_BMX;
    float* sdl  = sm + S_SDL;
    float* vc1  = sm + S_VC1;
    float* vc2  = sm + S_VC2;
    float* vc3  = sm + S_VC3;
    float* pbf  = sm + S_PBF;
    float* pwT  = sm + S_PWT;
    float* aA   = sm + S_AA;
    float* psum = sm + S_PSUM;
    float* psq  = sm + S_PSQ;
    float* ppc  = sm + S_PPC;
    float* p1   = sm + S_P1;
    float* p2   = sm + S_P2;

    const int j32 = tid & 31;
    const int g8  = tid >> 5;

    const float bq_ = q_b[j32];
    const float bk_ = k_b[j32];
    const float bv_ = v_b[j32];
    const float bm_ = m_b[j32];

    float* xatt = gXATT + base;

    // ---------------- Phase 1: stage small tables + stats partials --------
    for (int idx = tid; idx < 1024; idx += NTHR) {
        int j = idx >> 5, i = idx & 31;
        aA[j * 33 + i] = gA32[idx];
    }
    for (int idx = tid; idx < 576; idx += NTHR) {
        int lo = idx / 24, l = idx % 24;
        pwT[l * 25 + lo] = p_w[idx];
    }
    for (int idx = tid; idx < 376; idx += NTHR) bmx[idx] = gBmixr[idx];
    if (tid < 24) pbf[tid] = p_b[tid];
    if (tid < 192) {
        int c = tid & 31, g = tid >> 5;
        float4 v = *(const float4*)(x + base + c * 216 + g * 4);
        float* xb = sm + S_XB0;
        int row = g * 4;
        xb[(row + 0) * 36 + c] = v.x;
        xb[(row + 1) * 36 + c] = v.y;
        xb[(row + 2) * 36 + c] = v.z;
        xb[(row + 3) * 36 + c] = v.w;
    }
    {
        int c = tid >> 3, part = tid & 7;
        const float* xp = x + base + c * 216 + part * 27;
        float s = 0.f, sq = 0.f;
#pragma unroll 9
        for (int k2 = 0; k2 < 27; ++k2) {
            float v = xp[k2];
            s += v; sq += v * v;
        }
        psum[c * 8 + part] = s;
        psq [c * 8 + part] = sq;
    }
    __syncthreads();

    // ---------------- Phase 2b: warp-0 scalar chain ----------------
    if (tid < 32) {
        const int c = tid;
        float s = 0.f, sq = 0.f;
#pragma unroll
        for (int p = 0; p < 8; ++p) { s += psum[c * 8 + p]; sq += psq[c * 8 + p]; }
        float pooled = s * (1.f / 216.f);
        float varu = (sq - s * s * (1.f / 216.f)) * (1.f / 215.f);
        float scalec = fmaxf(sqrtf(fmaxf(varu, 0.f)), 1e-3f);

        float mu = pooled;
#pragma unroll
        for (int o = 16; o > 0; o >>= 1) mu += __shfl_xor_sync(0xffffffffu, mu, o);
        mu *= (1.f / 32.f);
        float d = pooled - mu;
        float var = d * d;
#pragma unroll
        for (int o = 16; o > 0; o >>= 1) var += __shfl_xor_sync(0xffffffffu, var, o);
        var *= (1.f / 32.f);
        float pn = d * rsqrtf(var + 1e-5f) * ln_g[c] + ln_b[c];
        vc1[c] = pn; __syncwarp();

        float acc = rp_b1[c];
#pragma unroll
        for (int i = 0; i < 32; ++i) acc += vc1[i] * rp_w1[c * 32 + i];
        vc2[c] = geluf(acc); __syncwarp();

        acc = rp_b2[c];
#pragma unroll
        for (int i = 0; i < 32; ++i) acc += vc2[i] * rp_w2[c * 32 + i];
        vc1[c] = acc; __syncwarp();       // pooled_rule

        acc = mask_b[c];
#pragma unroll
        for (int i = 0; i < 32; ++i) acc += vc1[i] * mask_w[c * 32 + i];
        float M = sigmoidf_(acc);

        acc = val_b1[c];
#pragma unroll
        for (int i = 0; i < 32; ++i) acc += vc1[i] * val_w1[c * 32 + i];
        vc2[c] = geluf(acc); __syncwarp();

        acc = val_b2[c];
#pragma unroll
        for (int i = 0; i < 32; ++i) acc += vc2[i] * val_w2[c * 32 + i];
        float v32 = tanhf(acc) * scalec + pooled;
        float xdo = (1.f - M) * pooled + M * v32;

        float y = xdo;
#pragma unroll
        for (int it = 0; it < 3; ++it) {
            vc3[c] = y; __syncwarp();
            float a2 = xdo;
#pragma unroll
            for (int j = 0; j < 32; ++j) a2 += vc3[j] * aA[c * 33 + j];
            y = a2;
            __syncwarp();
        }
        sdl[c] = sigmoidf_(fuse_gate[0]) * (y - pooled);
    }
    __syncthreads();

    // ---------------- Phase 4: attention per context t ----------------
    for (int t = 0; t < 9; ++t) {
        float* xb = sm + ((t & 1) ? S_XB1 : S_XB0);
        float* xn = sm + ((t & 1) ? S_XB0 : S_XB1);

        // 4a: qkv projection + fuse add + cosine norm (shfl)
        {
            float aq[3], ak[3], av[3];
#pragma unroll
            for (int r = 0; r < 3; ++r) { aq[r] = bq_; ak[r] = bk_; av[r] = bv_; }
#pragma unroll
            for (int i4 = 0; i4 < 8; ++i4) {
                float4 sd4 = *(const float4*)&sdl[i4 * 4];
                float4 wq4 = *(const float4*)&gWQKV4[(i4 * 32 + j32) * 4];
                float4 wk4 = *(const float4*)&gWQKV4[1024 + (i4 * 32 + j32) * 4];
                float4 wv4 = *(const float4*)&gWQKV4[2048 + (i4 * 32 + j32) * 4];
#pragma unroll
                for (int r = 0; r < 3; ++r) {
                    float4 f4 = *(const float4*)&xb[(g8 * 3 + r) * 36 + i4 * 4];
                    float f0 = f4.x + sd4.x, f1 = f4.y + sd4.y;
                    float f2 = f4.z + sd4.z, f3 = f4.w + sd4.w;
                    aq[r] = fmaf(f0, wq4.x, aq[r]); aq[r] = fmaf(f1, wq4.y, aq[r]);
                    aq[r] = fmaf(f2, wq4.z, aq[r]); aq[r] = fmaf(f3, wq4.w, aq[r]);
                    ak[r] = fmaf(f0, wk4.x, ak[r]); ak[r] = fmaf(f1, wk4.y, ak[r]);
                    ak[r] = fmaf(f2, wk4.z, ak[r]); ak[r] = fmaf(f3, wk4.w, ak[r]);
                    av[r] = fmaf(f0, wv4.x, av[r]); av[r] = fmaf(f1, wv4.y, av[r]);
                    av[r] = fmaf(f2, wv4.z, av[r]); av[r] = fmaf(f3, wv4.w, av[r]);
                }
            }
#pragma unroll
            for (int r = 0; r < 3; ++r) {
                float n2 = aq[r] * aq[r];
                n2 += __shfl_xor_sync(0xffffffffu, n2, 1);
                n2 += __shfl_xor_sync(0xffffffffu, n2, 2);
                aq[r] *= 0.5f / fmaxf(sqrtf(n2), 1e-12f);   // 1/sqrt(HD)=0.5 folded
                n2 = ak[r] * ak[r];
                n2 += __shfl_xor_sync(0xffffffffu, n2, 1);
                n2 += __shfl_xor_sync(0xffffffffu, n2, 2);
                ak[r] *= 1.f / fmaxf(sqrtf(n2), 1e-12f);
                n2 = av[r] * av[r];
                n2 += __shfl_xor_sync(0xffffffffu, n2, 1);
                n2 += __shfl_xor_sync(0xffffffffu, n2, 2);
                av[r] *= 1.f / fmaxf(sqrtf(n2), 1e-12f);
                q3[(g8 * 3 + r) * 36 + j32] = aq[r];
                k3[(g8 * 3 + r) * 36 + j32] = ak[r];
                v3[(g8 * 3 + r) * 36 + j32] = av[r];
            }
        }
        __syncthreads();

        // 4cde merged (warps 0-5), r-serialized to cap registers:
        // logits -> W_logit mix + bias -> shfl softmax -> W_ctx mix.
        // warps 6-7: prefetch next t's x rows.
        if (tid < 192) {
            const int i = tid >> 3, jg = tid & 7;
            float ml[8][3];
#pragma unroll
            for (int r = 0; r < 3; ++r) {
                const int j = jg * 3 + r;
                float raw[8];
#pragma unroll
                for (int h = 0; h < 8; ++h) {
                    float4 qh = *(const float4*)&q3[i * 36 + h * 4];
                    float4 kv = *(const float4*)&k3[j * 36 + h * 4];
                    raw[h] = qh.x*kv.x + qh.y*kv.y + qh.z*kv.z + qh.w*kv.w;
                }
#pragma unroll
                for (int Ho = 0; Ho < 8; ++Ho) {
                    float acc = bmx[Ho * 47 + i - j + 23];
#pragma unroll
                    for (int h = 0; h < 8; ++h)
                        acc = fmaf(raw[h], cWL[h * 8 + Ho], acc);
                    ml[Ho][r] = acc;
                }
            }
#pragma unroll
            for (int Ho = 0; Ho < 8; ++Ho) {
                float m = fmaxf(ml[Ho][0], fmaxf(ml[Ho][1], ml[Ho][2]));
                m = fmaxf(m, __shfl_xor_sync(0xffffffffu, m, 1));
                m = fmaxf(m, __shfl_xor_sync(0xffffffffu, m, 2));
                m = fmaxf(m, __shfl_xor_sync(0xffffffffu, m, 4));
                float s0 = __expf(ml[Ho][0] - m);
                float s1 = __expf(ml[Ho][1] - m);
                float s2 = __expf(ml[Ho][2] - m);
                float ssum = s0 + s1 + s2;
                ssum += __shfl_xor_sync(0xffffffffu, ssum, 1);
                ssum += __shfl_xor_sync(0xffffffffu, ssum, 2);
                ssum += __shfl_xor_sync(0xffffffffu, ssum, 4);
                float inv = 1.f / ssum;
                ml[Ho][0] = s0 * inv; ml[Ho][1] = s1 * inv; ml[Ho][2] = s2 * inv;
            }
#pragma unroll
            for (int Ho = 0; Ho < 8; ++Ho) {
#pragma unroll
                for (int r = 0; r < 3; ++r) {
                    float acc = 0.f;
#pragma unroll
                    for (int h = 0; h < 8; ++h)
                        acc = fmaf(ml[h][r], cWC[h * 8 + Ho], acc);
                    smx[Ho * 676 + i * 28 + jg * 3 + r] = acc;
                }
            }
        } else if (t < 8) {
            int lt = tid - 192;
#pragma unroll
            for (int k = 0; k < 3; ++k) {
                int idx4 = lt + k * 64;
                int c = idx4 & 31, g = idx4 >> 5;
                float4 v = *(const float4*)(x + base + c * 216 + (t + 1) * 24 + g * 4);
                int row = g * 4;
                xn[(row + 0) * 36 + c] = v.x;
                xn[(row + 1) * 36 + c] = v.y;
                xn[(row + 2) * 36 + c] = v.z;
                xn[(row + 3) * 36 + c] = v.w;
            }
        }
        __syncthreads();

        // 4f: AV -> att into q3 (3 rows per thread-group)
        {
            const int h = j32 >> 2;
            float acc[3] = {0.f, 0.f, 0.f};
#pragma unroll
            for (int j4 = 0; j4 < 6; ++j4) {
                float s4[3][4];
#pragma unroll
                for (int r = 0; r < 3; ++r) {
                    float4 tv = *(const float4*)&smx[h * 676 + (g8 * 3 + r) * 28 + j4 * 4];
                    s4[r][0] = tv.x; s4[r][1] = tv.y; s4[r][2] = tv.z; s4[r][3] = tv.w;
                }
#pragma unroll
                for (int s = 0; s < 4; ++s) {
                    float vv = v3[(j4 * 4 + s) * 36 + j32];
#pragma unroll
                    for (int r = 0; r < 3; ++r)
                        acc[r] = fmaf(s4[r][s], vv, acc[r]);
                }
            }
#pragma unroll
            for (int r = 0; r < 3; ++r)
                q3[(g8 * 3 + r) * 36 + j32] = acc[r];
        }
        __syncthreads();

        // 4g: output projection -> gXATT rows of this t (coalesced)
        {
            float am[3];
#pragma unroll
            for (int r = 0; r < 3; ++r) am[r] = bm_;
#pragma unroll
            for (int i4 = 0; i4 < 8; ++i4) {
                float4 wm_ = *(const float4*)&gWM4[(i4 * 32 + j32) * 4];
#pragma unroll
                for (int r = 0; r < 3; ++r) {
                    float4 a4 = *(const float4*)&q3[(g8 * 3 + r) * 36 + i4 * 4];
                    am[r] = fmaf(a4.x, wm_.x, am[r]); am[r] = fmaf(a4.y, wm_.y, am[r]);
                    am[r] = fmaf(a4.z, wm_.z, am[r]); am[r] = fmaf(a4.w, wm_.w, am[r]);
                }
            }
#pragma unroll
            for (int r = 0; r < 3; ++r)
                xatt[(t * 24 + g8 * 3 + r) * 32 + j32] = am[r];
        }
        __syncthreads();
    }

    // ---------------- Phase 5: conv over contexts (all 256 threads) --------
    for (int idx = tid; idx < 768; idx += NTHR) {
        int o = idx / 24, l = idx % 24;
        ppc[o * 25 + l] = gPPC[idx];
    }
    __syncthreads();
    {
        const int lbase = g8 * 3;
        float acc[3];
#pragma unroll
        for (int r = 0; r < 3; ++r) acc[r] = ppc[j32 * 25 + lbase + r];
#pragma unroll
        for (int kt = 0; kt < 8; ++kt) {
#pragma unroll
            for (int i4 = 0; i4 < 8; ++i4) {
                float4 w4 = *(const float4*)&gCWT2[((kt * 8 + i4) * 32 + j32) * 4];
#pragma unroll
                for (int r = 0; r < 3; ++r) {
                    float4 f4 = *(const float4*)&xatt[(kt * 24 + lbase + r) * 32 + i4 * 4];
                    acc[r] = fmaf(f4.x, w4.x, acc[r]);
                    acc[r] = fmaf(f4.y, w4.y, acc[r]);
                    acc[r] = fmaf(f4.z, w4.z, acc[r]);
                    acc[r] = fmaf(f4.w, w4.w, acc[r]);
                }
            }
        }
#pragma unroll
        for (int r = 0; r < 3; ++r)
            p1[j32 * 25 + lbase + r] = fmaxf(acc[r], 0.f);
    }
    __syncthreads();

    // ---------------- Phase 6: token linear ----------------
    for (int idx = tid; idx < 768; idx += NTHR) {
        int o = idx / 24, lo = idx % 24;
        float acc = pbf[lo];
#pragma unroll
        for (int l = 0; l < 24; ++l)
            acc = fmaf(p1[o * 25 + l], pwT[l * 25 + lo], acc);
        p2[o * 25 + lo] = acc;
    }
    __syncthreads();

    // ---------------- Phase 7: output ----------------
    for (int idx4 = tid; idx4 < 1728; idx4 += NTHR) {
        int c = idx4 & 31, g = idx4 >> 5;
        int tl = g * 4;
        float4 v;
        v.x = xatt[(tl + 0) * 32 + c];
        v.y = xatt[(tl + 1) * 32 + c];
        v.z = xatt[(tl + 2) * 32 + c];
        v.w = xatt[(tl + 3) * 32 + c];
        if (g >= 48) {
            v.x -= p2[c * 25 + (tl - 192)];
            v.y -= p2[c * 25 + (tl - 191)];
            v.z -= p2[c * 25 + (tl - 190)];
            v.w -= p2[c * 25 + (tl - 189)];
        }
        *(float4*)(out + base + c * 216 + tl) = v;
    }
}

extern "C" void kernel_launch(void* const* d_in, const int* in_sizes, int n_in,
                              void* d_out, int out_size) {
    const float* x        = (const float*)d_in[0];
    const float* ln_g     = (const float*)d_in[1];
    const float* ln_b     = (const float*)d_in[2];
    const float* rp_w1    = (const float*)d_in[3];
    const float* rp_b1    = (const float*)d_in[4];
    const float* rp_w2    = (const float*)d_in[5];
    const float* rp_b2    = (const float*)d_in[6];
    const float* W_causal = (const float*)d_in[7];
    const float* mask_w   = (const float*)d_in[8];
    const float* mask_b   = (const float*)d_in[9];
    const float* val_w1   = (const float*)d_in[10];
    const float* val_b1   = (const float*)d_in[11];
    const float* val_w2   = (const float*)d_in[12];
    const float* val_b2   = (const float*)d_in[13];
    const float* fuse_g   = (const float*)d_in[14];
    const float* q_w      = (const float*)d_in[15];
    const float* q_b      = (const float*)d_in[16];
    const float* k_w      = (const float*)d_in[17];
    const float* k_b      = (const float*)d_in[18];
    const float* v_w      = (const float*)d_in[19];
    const float* v_b      = (const float*)d_in[20];
    const float* m_w      = (const float*)d_in[21];
    const float* m_b      = (const float*)d_in[22];
    const float* W_logit  = (const float*)d_in[23];
    const float* W_ctx    = (const float*)d_in[24];
    const float* rpb      = (const float*)d_in[25];
    const float* pre_p    = (const float*)d_in[26];
    const float* conv_w   = (const float*)d_in[27];
    const float* conv_b   = (const float*)d_in[28];
    const float* p_w      = (const float*)d_in[29];
    const float* p_b      = (const float*)d_in[30];
    float* out = (float*)d_out;

    const int smem_bytes = S_TOTAL * 4;
    cudaFuncSetAttribute(prb_kernel, cudaFuncAttributeMaxDynamicSharedMemorySize,
                         smem_bytes);

    cudaMemcpyToSymbolAsync(cWL, W_logit, 64 * sizeof(float), 0,
                            cudaMemcpyDeviceToDevice);
    cudaMemcpyToSymbolAsync(cWC, W_ctx, 64 * sizeof(float), 0,
                            cudaMemcpyDeviceToDevice);

    prb_precompute<<<1, 256>>>(W_causal, W_logit, rpb, conv_w, conv_b, pre_p,
                               q_w, k_w, v_w, m_w);

    int B = in_sizes[0] / 6912;
    prb_kernel<<<B, NTHR, smem_bytes>>>(
        x, ln_g, ln_b, rp_w1, rp_b1, rp_w2, rp_b2,
        mask_w, mask_b, val_w1, val_b1, val_w2, val_b2, fuse_g,
        q_b, k_b, v_b, m_b, p_w, p_b, out);
}